// round 14
// baseline (speedup 1.0000x reference)
#include <cuda_runtime.h>
#include <math_constants.h>

#define BN_SCALE 0.9999950000374997f

#define BB 8
#define N1 2048
#define M1 512
#define KK1 20
#define KK2 10

// ---------------- scratch ----------------
__device__ float g_D[(size_t)BB * N1 * N1];
__device__ float g_P[BB * 1024 * M1];
__device__ float g_normA[BB * N1];
__device__ int   g_idx1[BB * N1 * KK1];
__device__ int   g_idx2[BB * N1 * KK1];
__device__ int   g_idxA[BB * M1 * KK1];
__device__ int   g_idx3[BB * M1 * KK2];
__device__ int   g_idx4[BB * M1 * KK2];
__device__ float g_y[BB * 131072];
__device__ float g_u[BB * 131072];
__device__ float g_xt1_cn[BB * 128 * N1];
__device__ float g_xt1_nc[BB * N1 * 128];
__device__ unsigned g_venc[BB * 2048];
__device__ int   g_fpsidx[BB * M1];
__device__ float g_node1[BB * 3 * M1];
__device__ float g_xm[BB * 256 * M1];
__device__ float g_x34[BB * 512 * M1];
__device__ float g_Wd1[64 * 3],    g_Wu1[64 * 3];
__device__ float g_Wd2[64 * 64],   g_Wu2[64 * 64];
__device__ float g_Wd3[256 * 256], g_Wu3[256 * 256];
__device__ float g_Wd4[256 * 256], g_Wu4[256 * 256];
__device__ float g_Wt1[128 * 1024];
__device__ float g_Wt2[512 * 1024];

__device__ __forceinline__ unsigned fenc(float f) {
    unsigned u = __float_as_uint(f);
    return (u & 0x80000000u) ? ~u : (u | 0x80000000u);
}
__device__ __forceinline__ float fdec(unsigned u) {
    return __uint_as_float((u & 0x80000000u) ? (u & 0x7fffffffu) : ~u);
}

__device__ __forceinline__ bool tk_better(float a, int ia, float b, int ib) {
    return a > b || (a == b && ia < ib);
}

// Sorted-insert with STRICT > (per-lane scan order is monotonic in index)
#define TK_INSERT(cv, ci)                                             \
    if ((cv) > bv3) {                                                 \
        if ((cv) > bv0) {                                             \
            bv3 = bv2; bi3 = bi2; bv2 = bv1; bi2 = bi1;               \
            bv1 = bv0; bi1 = bi0; bv0 = (cv); bi0 = (ci);             \
        } else if ((cv) > bv1) {                                      \
            bv3 = bv2; bi3 = bi2; bv2 = bv1; bi2 = bi1;               \
            bv1 = (cv); bi1 = (ci);                                   \
        } else if ((cv) > bv2) {                                      \
            bv3 = bv2; bi3 = bi2; bv2 = (cv); bi2 = (ci);             \
        } else {                                                      \
            bv3 = (cv); bi3 = (ci);                                   \
        }                                                             \
    }

// ---------------- streaming warp top-k: scalar functor source ----------------
template <int NPL, int KSEL, typename F>
__device__ __forceinline__ void warp_topk_f(const F& getv, int lane, int* __restrict__ orow) {
    unsigned long long zap = 0ull;
    float bv0, bv1, bv2, bv3;
    int bi0, bi1, bi2, bi3;

#define TK_RESET()                                                    \
    bv0 = bv1 = bv2 = bv3 = -CUDART_INF_F;                            \
    bi0 = bi1 = bi2 = bi3 = 1 << 30;

#define TK_SCAN_FIRST()                                               \
    {                                                                 \
        TK_RESET()                                                    \
        _Pragma("unroll")                                             \
        for (int s = 0; s < NPL; s++) {                               \
            float cv = getv(s);                                       \
            int ci = s * 32 + lane;                                   \
            TK_INSERT(cv, ci)                                         \
        }                                                             \
    }

#define TK_SCAN()                                                     \
    {                                                                 \
        TK_RESET()                                                    \
        _Pragma("unroll")                                             \
        for (int s = 0; s < NPL; s++) {                               \
            if ((zap >> s) & 1ull) continue;                          \
            float cv = getv(s);                                       \
            int ci = s * 32 + lane;                                   \
            TK_INSERT(cv, ci)                                         \
        }                                                             \
    }

    TK_SCAN_FIRST()
    for (int r = 0; r < KSEL; r++) {
        if (bi0 == (1 << 30)) { TK_SCAN() }
        float wb = bv0; int wi = bi0;
#pragma unroll
        for (int off = 16; off > 0; off >>= 1) {
            float ov = __shfl_xor_sync(0xffffffffu, wb, off);
            int oi = __shfl_xor_sync(0xffffffffu, wi, off);
            if (tk_better(ov, oi, wb, wi)) { wb = ov; wi = oi; }
        }
        if (lane == 0) orow[r] = wi;
        if ((wi & 31) == lane) {
            zap |= 1ull << (wi >> 5);
            bv0 = bv1; bi0 = bi1;
            bv1 = bv2; bi1 = bi2;
            bv2 = bv3; bi2 = bi3;
            bv3 = -CUDART_INF_F; bi3 = 1 << 30;
        }
    }
#undef TK_SCAN
#undef TK_SCAN_FIRST
#undef TK_RESET
}

// ---------------- streaming warp top-k: float4 D-row source, group-gated ----------------
// Per-quad gate: if max(quad) <= bv3 no element can pass the strict-> insert.
template <int NCHUNK, int KSEL>
__device__ __forceinline__ void warp_topk_d4(const float4* __restrict__ drow4, int lane,
                                             int* __restrict__ orow) {
    unsigned long long zap = 0ull;
    float bv0, bv1, bv2, bv3;
    int bi0, bi1, bi2, bi3;

#define TK_RESET()                                                    \
    bv0 = bv1 = bv2 = bv3 = -CUDART_INF_F;                            \
    bi0 = bi1 = bi2 = bi3 = 1 << 30;

#define TK_SCAN_D4_FIRST()                                            \
    {                                                                 \
        TK_RESET()                                                    \
        _Pragma("unroll 4")                                           \
        for (int c = 0; c < NCHUNK; c++) {                            \
            float4 f = drow4[c * 32 + lane];                          \
            float m4 = fmaxf(fmaxf(f.x, f.y), fmaxf(f.z, f.w));       \
            if (m4 > bv3) {                                           \
                float vals[4] = {f.x, f.y, f.z, f.w};                 \
                _Pragma("unroll")                                     \
                for (int q = 0; q < 4; q++) {                         \
                    float cv = vals[q];                               \
                    int ci = c * 128 + lane * 4 + q;                  \
                    TK_INSERT(cv, ci)                                 \
                }                                                     \
            }                                                         \
        }                                                             \
    }

#define TK_SCAN_D4()                                                  \
    {                                                                 \
        TK_RESET()                                                    \
        _Pragma("unroll 4")                                           \
        for (int c = 0; c < NCHUNK; c++) {                            \
            float4 f = drow4[c * 32 + lane];                          \
            float vals[4] = {f.x, f.y, f.z, f.w};                     \
            _Pragma("unroll")                                         \
            for (int q = 0; q < 4; q++)                               \
                if ((zap >> (c * 4 + q)) & 1ull) vals[q] = -CUDART_INF_F; \
            float m4 = fmaxf(fmaxf(vals[0], vals[1]), fmaxf(vals[2], vals[3])); \
            if (m4 > bv3) {                                           \
                _Pragma("unroll")                                     \
                for (int q = 0; q < 4; q++) {                         \
                    float cv = vals[q];                               \
                    int ci = c * 128 + lane * 4 + q;                  \
                    TK_INSERT(cv, ci)                                 \
                }                                                     \
            }                                                         \
        }                                                             \
    }

    TK_SCAN_D4_FIRST()
    for (int r = 0; r < KSEL; r++) {
        if (bi0 == (1 << 30)) { TK_SCAN_D4() }
        float wb = bv0; int wi = bi0;
#pragma unroll
        for (int off = 16; off > 0; off >>= 1) {
            float ov = __shfl_xor_sync(0xffffffffu, wb, off);
            int oi = __shfl_xor_sync(0xffffffffu, wi, off);
            if (tk_better(ov, oi, wb, wi)) { wb = ov; wi = oi; }
        }
        if (lane == 0) orow[r] = wi;
        if (((wi >> 2) & 31) == lane) {
            int c = wi >> 7, q = wi & 3;
            zap |= 1ull << (c * 4 + q);
            bv0 = bv1; bi0 = bi1;
            bv1 = bv2; bi1 = bi2;
            bv2 = bv3; bi2 = bi3;
            bv3 = -CUDART_INF_F; bi3 = 1 << 30;
        }
    }
#undef TK_SCAN_D4
#undef TK_SCAN_D4_FIRST
#undef TK_RESET
}

// ---------------- shared-memory structs ----------------
struct SmemStart {
    float a[N1], b[N1], c[N1], d[N1];
    float wv[2][8];
    int wi[2][8];
    int sIdx[M1];
};
struct SmemG {
    float As[2][8][128];
    float Bs[2][8][128];
};
struct SmemDual {
    float Wds[16][65];
    float Wus[16][65];
    float Xs[16][65];
};
// mid2 is register-bound at 2 blocks/SM (regs=127), so a 33KB union is free
union SmemMid2 { SmemG g; SmemDual d; SmemStart k; };

// ---------------- small bodies ----------------
__device__ void prepw_body(const float* __restrict__ W, float* __restrict__ WdT,
                           float* __restrict__ WuT, int O, int C, int vb) {
    int i = vb * 256 + threadIdx.x;
    if (i >= O * C) return;
    int o = i / C, c = i % C;
    float wd = W[o * 2 * C + c];
    float wc = W[o * 2 * C + C + c];
    WdT[(size_t)c * O + o] = wd;
    WuT[(size_t)c * O + o] = wc - wd;
}

__device__ void wtrans_body(const float* __restrict__ W, float* __restrict__ Wt,
                            int O, int C, int vb) {
    int i = vb * 256 + threadIdx.x;
    if (i >= O * C) return;
    int o = i / C, c = i % C;
    Wt[(size_t)c * O + o] = W[(size_t)o * C + c];
}

__device__ void initv_body(unsigned* venc, int vb) {
    int i = vb * 256 + threadIdx.x;
    if (i < BB * 2048) venc[i] = 0u;
}

template <int KSEL>
__device__ void knn3d_body(const float* __restrict__ Q, const float* __restrict__ P,
                           int M, int* __restrict__ idxOut, long qbs, long pbs,
                           int mBase, int b, SmemStart& S) {
    int tid = threadIdx.x;
    int nt = blockDim.x;
    const float* Pb = P + (size_t)b * pbs;
    for (int j = tid; j < N1; j += nt) {
        float vx = Pb[j], vy = Pb[N1 + j], vz = Pb[2 * N1 + j];
        S.a[j] = vx; S.b[j] = vy; S.c[j] = vz;
        S.d[j] = __fadd_rn(__fadd_rn(__fmul_rn(vx, vx), __fmul_rn(vy, vy)),
                           __fmul_rn(vz, vz));
    }
    __syncthreads();
    int warp = tid >> 5, lane = tid & 31;
    int m = mBase + warp;
    const float* Qb = Q + (size_t)b * qbs;
    float qx = Qb[m], qy = Qb[M + m], qz = Qb[2 * M + m];
    auto getv = [&](int s) {
        int j = s * 32 + lane;
        float inner = fmaf(qx, S.a[j], fmaf(qy, S.b[j], qz * S.c[j]));
        return 2.f * inner - S.d[j];
    };
    warp_topk_f<64, KSEL>(getv, lane, idxOut + ((size_t)b * M + m) * KSEL);
}

__device__ void fps_body(const float* __restrict__ xyz, int* __restrict__ fpsidx,
                         float* __restrict__ node1, float* __restrict__ outNode,
                         int b, SmemStart& S) {
    int tid = threadIdx.x;
    int warp = tid >> 5, lane = tid & 31;
    const float* xb = xyz + (size_t)b * 3 * N1;
    for (int j = tid; j < N1; j += 256) {
        S.a[j] = xb[j];
        S.b[j] = xb[N1 + j];
        S.c[j] = xb[2 * N1 + j];
        S.d[j] = 1e10f;
    }
    __syncthreads();
    int last = 0;
    for (int it = 0; it < M1; it++) {
        int par = it & 1;
        if (tid == 0) { S.sIdx[it] = last; fpsidx[b * M1 + it] = last; }
        float px = S.a[last], py = S.b[last], pz = S.c[last];
        float bmax = -CUDART_INF_F;
        int bidx = 0;
#pragma unroll
        for (int r = 0; r < 8; r++) {
            int j = tid + r * 256;
            float dx = __fsub_rn(S.a[j], px);
            float dy = __fsub_rn(S.b[j], py);
            float dz = __fsub_rn(S.c[j], pz);
            float dd = __fadd_rn(__fadd_rn(__fmul_rn(dx, dx), __fmul_rn(dy, dy)),
                                 __fmul_rn(dz, dz));
            float nd = fminf(S.d[j], dd);
            S.d[j] = nd;
            if (nd > bmax) { bmax = nd; bidx = j; }
        }
#pragma unroll
        for (int off = 16; off > 0; off >>= 1) {
            float ov = __shfl_xor_sync(0xffffffffu, bmax, off);
            int oi = __shfl_xor_sync(0xffffffffu, bidx, off);
            if (ov > bmax || (ov == bmax && oi < bidx)) { bmax = ov; bidx = oi; }
        }
        if (lane == 0) { S.wv[par][warp] = bmax; S.wi[par][warp] = bidx; }
        __syncthreads();
        float bv = S.wv[par][0];
        int bi = S.wi[par][0];
#pragma unroll
        for (int w = 1; w < 8; w++) {
            float ov = S.wv[par][w];
            int oi = S.wi[par][w];
            if (ov > bv || (ov == bv && oi < bi)) { bv = ov; bi = oi; }
        }
        last = bi;
    }
    __syncthreads();
    for (int m = tid; m < M1; m += 256) {
        int j = S.sIdx[m];
        float vx = S.a[j], vy = S.b[j], vz = S.c[j];
        node1[((size_t)b * 3 + 0) * M1 + m] = vx;
        node1[((size_t)b * 3 + 1) * M1 + m] = vy;
        node1[((size_t)b * 3 + 2) * M1 + m] = vz;
        outNode[((size_t)b * 3 + 0) * M1 + m] = vx;
        outNode[((size_t)b * 3 + 1) * M1 + m] = vy;
        outNode[((size_t)b * 3 + 2) * M1 + m] = vz;
    }
}

__device__ void gemm_dual_body(const float* __restrict__ WdT, const float* __restrict__ WuT,
                               const float* __restrict__ X,
                               float* __restrict__ y, float* __restrict__ u,
                               int O, int C, int N, long xbs,
                               int bx, int by, int bz, SmemDual& S) {
    int o0 = by * 64, n0 = bx * 64;
    int t = threadIdx.x;
    int tx = t & 15, ty = t >> 4;
    const float* Xb = X + (size_t)bz * xbs;
    float accd[4][4], accu[4][4];
#pragma unroll
    for (int i = 0; i < 4; i++)
#pragma unroll
        for (int j = 0; j < 4; j++) { accd[i][j] = 0.f; accu[i][j] = 0.f; }

    for (int c0 = 0; c0 < C; c0 += 16) {
#pragma unroll
        for (int l = 0; l < 4; l++) {
            int e = t + l * 256;
            int wo = e & 63, wc = e >> 6;
            float vd = 0.f, vu = 0.f;
            if (o0 + wo < O && c0 + wc < C) {
                vd = WdT[(size_t)(c0 + wc) * O + o0 + wo];
                vu = WuT[(size_t)(c0 + wc) * O + o0 + wo];
            }
            S.Wds[wc][wo] = vd;
            S.Wus[wc][wo] = vu;
            float xv = 0.f;
            if (c0 + wc < C && n0 + wo < N) xv = Xb[(size_t)(c0 + wc) * N + n0 + wo];
            S.Xs[wc][wo] = xv;
        }
        __syncthreads();
#pragma unroll
        for (int kk = 0; kk < 16; kk++) {
            float wd[4], wu[4], xv[4];
#pragma unroll
            for (int i = 0; i < 4; i++) { wd[i] = S.Wds[kk][ty + 16 * i]; wu[i] = S.Wus[kk][ty + 16 * i]; }
#pragma unroll
            for (int j = 0; j < 4; j++) xv[j] = S.Xs[kk][tx + 16 * j];
#pragma unroll
            for (int i = 0; i < 4; i++)
#pragma unroll
                for (int j = 0; j < 4; j++) {
                    accd[i][j] += wd[i] * xv[j];
                    accu[i][j] += wu[i] * xv[j];
                }
        }
        __syncthreads();
    }
#pragma unroll
    for (int i = 0; i < 4; i++) {
        int o = o0 + ty + 16 * i;
        if (o >= O) continue;
#pragma unroll
        for (int j = 0; j < 4; j++) {
            int n = n0 + tx + 16 * j;
            if (n >= N) continue;
            y[((size_t)bz * N + n) * O + o] = accd[i][j];
            u[((size_t)bz * N + n) * O + o] = accu[i][j];
        }
    }
}

// ================= 128x128x8 GEMM body =================
template <int MODE>
__device__ void gemm128_body(
    const float* __restrict__ A, const float* __restrict__ B, float* __restrict__ out,
    int M, int N, int C, long ldA, long ldB, long abs_, long bbs,
    const float* __restrict__ p1, const float* __restrict__ p2,
    unsigned* __restrict__ venc, int voff, int ldOut,
    float* __restrict__ P, int ldP,
    int bx, int by, int bz, SmemG& S) {
    int m0 = by * 128, n0 = bx * 128;
    int t = threadIdx.x;
    int tx = t & 15, ty = t >> 4;
    int lr = t >> 5;
    int lc = (t & 31) * 4;
    const float* aSrc = A + (size_t)bz * abs_ + (size_t)lr * ldA + m0 + lc;
    const float* bSrc = B + (size_t)bz * bbs + (size_t)lr * ldB + n0 + lc;
    float acc[8][8];
#pragma unroll
    for (int i = 0; i < 8; i++)
#pragma unroll
        for (int j = 0; j < 8; j++) acc[i][j] = 0.f;

    int nc = C >> 3;
    float4 av = *(const float4*)aSrc;
    float4 bv = *(const float4*)bSrc;
    *(float4*)&S.As[0][lr][lc] = av;
    *(float4*)&S.Bs[0][lr][lc] = bv;
    __syncthreads();
    int p = 0;
    for (int i = 0; i < nc; i++) {
        if (i + 1 < nc) {
            av = *(const float4*)(aSrc + (size_t)(i + 1) * 8 * ldA);
            bv = *(const float4*)(bSrc + (size_t)(i + 1) * 8 * ldB);
        }
#pragma unroll
        for (int k = 0; k < 8; k++) {
            float4 a0 = *(float4*)&S.As[p][k][ty * 4];
            float4 a1 = *(float4*)&S.As[p][k][64 + ty * 4];
            float4 b0 = *(float4*)&S.Bs[p][k][tx * 4];
            float4 b1 = *(float4*)&S.Bs[p][k][64 + tx * 4];
            float aa[8] = {a0.x, a0.y, a0.z, a0.w, a1.x, a1.y, a1.z, a1.w};
            float bb[8] = {b0.x, b0.y, b0.z, b0.w, b1.x, b1.y, b1.z, b1.w};
#pragma unroll
            for (int ii = 0; ii < 8; ii++)
#pragma unroll
                for (int jj = 0; jj < 8; jj++) acc[ii][jj] += aa[ii] * bb[jj];
        }
        if (i + 1 < nc) {
            *(float4*)&S.As[p ^ 1][lr][lc] = av;
            *(float4*)&S.Bs[p ^ 1][lr][lc] = bv;
            __syncthreads();
            p ^= 1;
        }
    }

    if (MODE == 0) {
#pragma unroll
        for (int i = 0; i < 8; i++) {
            int m = m0 + (i < 4 ? ty * 4 + i : 64 + ty * 4 + i - 4);
            float nq = p1[bz * M + m];
            float* orow = out + ((size_t)bz * M + m) * ldOut;
            float4 d0, d1;
            d0.x = 2.f * acc[i][0] - nq - p2[bz * N + n0 + tx * 4 + 0];
            d0.y = 2.f * acc[i][1] - nq - p2[bz * N + n0 + tx * 4 + 1];
            d0.z = 2.f * acc[i][2] - nq - p2[bz * N + n0 + tx * 4 + 2];
            d0.w = 2.f * acc[i][3] - nq - p2[bz * N + n0 + tx * 4 + 3];
            d1.x = 2.f * acc[i][4] - nq - p2[bz * N + n0 + 64 + tx * 4 + 0];
            d1.y = 2.f * acc[i][5] - nq - p2[bz * N + n0 + 64 + tx * 4 + 1];
            d1.z = 2.f * acc[i][6] - nq - p2[bz * N + n0 + 64 + tx * 4 + 2];
            d1.w = 2.f * acc[i][7] - nq - p2[bz * N + n0 + 64 + tx * 4 + 3];
            *(float4*)&orow[n0 + tx * 4] = d0;
            *(float4*)&orow[n0 + 64 + tx * 4] = d1;
        }
    } else if (MODE == 1 || MODE == 5) {
        if (MODE == 5) {
#pragma unroll
            for (int i = 0; i < 8; i++) {
                int m = m0 + (i < 4 ? ty * 4 + i : 64 + ty * 4 + i - 4);
                const float* prow = P + ((size_t)bz * M + m) * ldP;
                float4 q0 = *(const float4*)&prow[n0 + tx * 4];
                float4 q1 = *(const float4*)&prow[n0 + 64 + tx * 4];
                acc[i][0] += q0.x; acc[i][1] += q0.y; acc[i][2] += q0.z; acc[i][3] += q0.w;
                acc[i][4] += q1.x; acc[i][5] += q1.y; acc[i][6] += q1.z; acc[i][7] += q1.w;
            }
        }
#pragma unroll
        for (int i = 0; i < 8; i++) {
            int m = m0 + (i < 4 ? ty * 4 + i : 64 + ty * 4 + i - 4);
            float gs = p1[m] * BN_SCALE, bvv = p2[m];
            float mx = -CUDART_INF_F;
#pragma unroll
            for (int j = 0; j < 8; j++) {
                float h = acc[i][j] * gs + bvv;
                h = h >= 0.f ? h : 0.2f * h;
                mx = fmaxf(mx, h);
            }
#pragma unroll
            for (int off = 8; off > 0; off >>= 1)
                mx = fmaxf(mx, __shfl_xor_sync(0xffffffffu, mx, off));
            if (tx == 0) atomicMax(&venc[bz * 2048 + voff + m], fenc(mx));
        }
    } else if (MODE == 4) {
#pragma unroll
        for (int i = 0; i < 8; i++) {
            int m = m0 + (i < 4 ? ty * 4 + i : 64 + ty * 4 + i - 4);
            float* prow = P + ((size_t)bz * M + m) * ldP;
            float4 v0, v1;
            v0.x = acc[i][0]; v0.y = acc[i][1]; v0.z = acc[i][2]; v0.w = acc[i][3];
            v1.x = acc[i][4]; v1.y = acc[i][5]; v1.z = acc[i][6]; v1.w = acc[i][7];
            *(float4*)&prow[n0 + tx * 4] = v0;
            *(float4*)&prow[n0 + 64 + tx * 4] = v1;
        }
    } else {
#pragma unroll
        for (int jj = 0; jj < 8; jj++) {
            int n = n0 + (jj < 4 ? tx * 4 + jj : 64 + tx * 4 + jj - 4);
            float* orow = out + ((size_t)bz * N + n) * ldOut;
            float4 v0, v1;
            v0.x = acc[0][jj]; v0.y = acc[1][jj]; v0.z = acc[2][jj]; v0.w = acc[3][jj];
            v1.x = acc[4][jj]; v1.y = acc[5][jj]; v1.z = acc[6][jj]; v1.w = acc[7][jj];
            *(float4*)&orow[m0 + ty * 4] = v0;
            *(float4*)&orow[m0 + 64 + ty * 4] = v1;
        }
    }
}

// ---------------- dispatcher kernels ----------------
__global__ __launch_bounds__(256) void start_kernel(
    const float* __restrict__ x,
    const float* __restrict__ W1, const float* __restrict__ W2,
    const float* __restrict__ W3, const float* __restrict__ W4,
    const float* __restrict__ W2m, const float* __restrict__ W5,
    int* __restrict__ idx1, int* __restrict__ fpsidx,
    float* __restrict__ node1, float* __restrict__ outNode,
    float* Wd1, float* Wu1, float* Wd2, float* Wu2,
    float* Wd3, float* Wu3, float* Wd4, float* Wu4,
    float* Wt1, float* Wt2, unsigned* venc) {
    __shared__ SmemStart S;
    int blk = blockIdx.x;
    if (blk < 2048) {
        knn3d_body<KK1>(x, x, N1, idx1, 3L * N1, 3L * N1, (blk & 255) * 8, blk >> 8, S);
    } else if (blk < 2056) {
        fps_body(x, fpsidx, node1, outNode, blk - 2048, S);
    } else if (blk < 2057) {
        prepw_body(W1, Wd1, Wu1, 64, 3, blk - 2056);
    } else if (blk < 2073) {
        prepw_body(W2, Wd2, Wu2, 64, 64, blk - 2057);
    } else if (blk < 2329) {
        prepw_body(W3, Wd3, Wu3, 256, 256, blk - 2073);
    } else if (blk < 2585) {
        prepw_body(W4, Wd4, Wu4, 256, 256, blk - 2329);
    } else if (blk < 3097) {
        wtrans_body(W2m, Wt1, 1024, 128, blk - 2585);
    } else if (blk < 5145) {
        wtrans_body(W5, Wt2, 1024, 512, blk - 3097);
    } else {
        initv_body(venc, blk - 5145);
    }
}

// econv1 direct from coords
__global__ __launch_bounds__(64) void econv1_kernel(
    const float* __restrict__ x, const float* __restrict__ Wd1T, const float* __restrict__ Wu1T,
    const int* __restrict__ idx, const float* __restrict__ g, const float* __restrict__ bb,
    float* __restrict__ out_cn, float* __restrict__ out_nc, float* __restrict__ normOut) {
    __shared__ float sjx[KK1], sjy[KK1], sjz[KK1];
    __shared__ int sidx[KK1];
    __shared__ float s2[2];
    int o = threadIdx.x;
    int n = blockIdx.x;
    int b = blockIdx.y;
    const float* xb = x + (size_t)b * 3 * N1;
    if (o < KK1) sidx[o] = idx[((size_t)b * N1 + n) * KK1 + o];
    __syncthreads();
    if (o < KK1) {
        int j = sidx[o];
        sjx[o] = xb[j];
        sjy[o] = xb[N1 + j];
        sjz[o] = xb[2 * N1 + j];
    }
    __syncthreads();
    float wdx = Wd1T[o], wdy = Wd1T[64 + o], wdz = Wd1T[128 + o];
    float wux = Wu1T[o], wuy = Wu1T[64 + o], wuz = Wu1T[128 + o];
    float xn = xb[n], yn = xb[N1 + n], zn = xb[2 * N1 + n];
    float uu = wux * xn + wuy * yn + wuz * zn;
    float gs = g[o] * BN_SCALE, bv = bb[o];
    float m = -CUDART_INF_F;
#pragma unroll
    for (int t = 0; t < KK1; t++) {
        float h = wdx * sjx[t] + wdy * sjy[t] + wdz * sjz[t] + uu;
        h = h * gs + bv;
        h = h >= 0.f ? h : 0.2f * h;
        m = fmaxf(m, h);
    }
    out_cn[((size_t)b * 128 + o) * N1 + n] = m;
    out_nc[((size_t)b * N1 + n) * 128 + o] = m;
    float sq = m * m;
#pragma unroll
    for (int off = 16; off > 0; off >>= 1)
        sq += __shfl_xor_sync(0xffffffffu, sq, off);
    int warp = o >> 5, lane = o & 31;
    if (lane == 0) s2[warp] = sq;
    __syncthreads();
    if (o == 0) normOut[b * N1 + n] = s2[0] + s2[1];
}

// knn2 negdist (2048) + dual2 (256) + aggregate knn (512)
__global__ __launch_bounds__(256) void mid2_kernel(
    const float* __restrict__ xt1cn, const float* __restrict__ normA, float* __restrict__ D,
    const float* __restrict__ Wd2, const float* __restrict__ Wu2,
    float* __restrict__ y, float* __restrict__ u,
    const float* __restrict__ node1, const float* __restrict__ x, int* __restrict__ idxA) {
    __shared__ SmemMid2 S;
    int blk = blockIdx.x;
    if (blk < 2048) {
        gemm128_body<0>(xt1cn, xt1cn, D, N1, N1, 64, N1, N1, 128L * N1, 128L * N1,
                        normA, normA, nullptr, 0, N1, nullptr, 0,
                        blk & 15, (blk >> 4) & 15, blk >> 8, S.g);
    } else if (blk < 2304) {
        int i = blk - 2048;
        gemm_dual_body(Wd2, Wu2, xt1cn, y, u, 64, 64, N1, 128L * N1, i & 31, 0, i >> 5, S.d);
    } else {
        int i = blk - 2304;
        knn3d_body<KK1>(node1, x, M1, idxA, 3L * M1, 3L * N1, (i & 63) * 8, i >> 6, S.k);
    }
}

// pure float4 top-k from D (zero smem, occupancy-capped regs)
template <int NCHUNK, int KSEL>
__global__ __launch_bounds__(256, 3) void topk_d4_kernel(
    const float* __restrict__ D, int rows, int N, int* __restrict__ idxOut) {
    int wid = blockIdx.x * 8 + (threadIdx.x >> 5);
    int lane = threadIdx.x & 31;
    if (wid >= BB * rows) return;
    const float4* drow4 = (const float4*)(D + (size_t)wid * N);
    warp_topk_d4<NCHUNK, KSEL>(drow4, lane, idxOut + (size_t)wid * KSEL);
}

// negdist3 (128) + maxv1 full C=128 (1024)
__global__ __launch_bounds__(256) void nd3max_kernel(
    const float* __restrict__ xm, const float* __restrict__ normA, float* __restrict__ D,
    const float* __restrict__ Wt1, const float* __restrict__ xt1cn,
    const float* __restrict__ g2m, const float* __restrict__ b2m,
    unsigned* __restrict__ venc) {
    __shared__ SmemG S;
    int blk = blockIdx.x;
    if (blk < 128) {
        gemm128_body<0>(xm, xm, D, M1, M1, 256, M1, M1, 256L * M1, 256L * M1,
                        normA, normA, nullptr, 0, M1, nullptr, 0,
                        blk & 3, (blk >> 2) & 3, blk >> 4, S);
    } else {
        int i = blk - 128;
        gemm128_body<1>(Wt1, xt1cn, nullptr, 1024, N1, 128, 1024, N1, 0, 128L * N1,
                        g2m, b2m, venc, 0, 0, nullptr, 0,
                        i & 15, (i >> 4) & 7, i >> 7, S);
    }
}

// topk3 (512) + y3 (64) + u3 (64)
__global__ __launch_bounds__(256) void tk3_kernel(
    const float* __restrict__ D, int* __restrict__ idx3,
    const float* __restrict__ Wd3, const float* __restrict__ Wu3,
    const float* __restrict__ xm, float* __restrict__ y, float* __restrict__ u) {
    __shared__ SmemG S;
    int blk = blockIdx.x;
    if (blk < 512) {
        int wid = blk * 8 + (threadIdx.x >> 5);
        int lane = threadIdx.x & 31;
        const float4* drow4 = (const float4*)(D + (size_t)wid * M1);
        warp_topk_d4<4, KK2>(drow4, lane, idx3 + (size_t)wid * KK2);
    } else if (blk < 576) {
        int i = blk - 512;
        gemm128_body<2>(Wd3, xm, y, 256, M1, 256, 256, M1, 0, 256L * M1,
                        nullptr, nullptr, nullptr, 0, 256, nullptr, 0,
                        i & 3, (i >> 2) & 1, i >> 3, S);
    } else {
        int i = blk - 576;
        gemm128_body<2>(Wu3, xm, u, 256, M1, 256, 256, M1, 0, 256L * M1,
                        nullptr, nullptr, nullptr, 0, 256, nullptr, 0,
                        i & 3, (i >> 2) & 1, i >> 3, S);
    }
}

// negdist4 (128) + y4 (64) + u4 (64) + maxv2a partial (256)
__global__ __launch_bounds__(256) void fusedA_kernel(
    const float* __restrict__ x34, const float* __restrict__ normA, float* __restrict__ D,
    const float* __restrict__ Wd4, const float* __restrict__ Wu4,
    float* __restrict__ y, float* __restrict__ u,
    const float* __restrict__ Wt2, float* __restrict__ P) {
    __shared__ SmemG S;
    int blk = blockIdx.x;
    if (blk < 128) {
        gemm128_body<0>(x34, x34, D, M1, M1, 256, M1, M1, 512L * M1, 512L * M1,
                        normA, normA, nullptr, 0, M1, nullptr, 0,
                        blk & 3, (blk >> 2) & 3, blk >> 4, S);
    } else if (blk < 192) {
        int i = blk - 128;
        gemm128_body<2>(Wd4, x34, y, 256, M1, 256, 256, M1, 0, 512L * M1,
                        nullptr, nullptr, nullptr, 0, 256, nullptr, 0,
                        i & 3, (i >> 2) & 1, i >> 3, S);
    } else if (blk < 256) {
        int i = blk - 192;
        gemm128_body<2>(Wu4, x34, u, 256, M1, 256, 256, M1, 0, 512L * M1,
                        nullptr, nullptr, nullptr, 0, 256, nullptr, 0,
                        i & 3, (i >> 2) & 1, i >> 3, S);
    } else {
        int i = blk - 256;
        gemm128_body<4>(Wt2, x34, nullptr, 1024, M1, 256, 1024, M1, 0, 512L * M1,
                        nullptr, nullptr, nullptr, 0, 0, P, M1,
                        i & 3, (i >> 2) & 7, i >> 5, S);
    }
}

// maxv2 final
__global__ __launch_bounds__(256) void maxv2b_kernel(
    const float* __restrict__ Wt2, const float* __restrict__ x34,
    const float* __restrict__ g5, const float* __restrict__ b5,
    unsigned* __restrict__ venc, float* __restrict__ P) {
    __shared__ SmemG S;
    int blk = blockIdx.x;
    gemm128_body<5>(Wt2 + 256 * 1024, x34 + 256L * M1, nullptr, 1024, M1, 256, 1024, M1,
                    0, 512L * M1, g5, b5, venc, 1024, 0, P, M1,
                    blk & 3, (blk >> 2) & 7, blk >> 5, S);
}

// ---------------- edge conv epilogue (layers 2..4) ----------------
template <int K, int DO_NORM>
__global__ void econv_kernel(const float* __restrict__ y, const float* __restrict__ u,
                             const int* __restrict__ idx, int O, int N,
                             const float* __restrict__ g, const float* __restrict__ bb,
                             float* __restrict__ out_cn, int Ctot, int coff,
                             float* __restrict__ out_nc, float* __restrict__ normOut) {
    __shared__ float s2[8];
    int o = threadIdx.x;
    int n = blockIdx.x;
    int b = blockIdx.y;
    const float* yb = y + (size_t)b * N * O;
    float uu = u[((size_t)b * N + n) * O + o];
    float gs = g[o] * BN_SCALE, bv = bb[o];
    const int* irow = idx + ((size_t)b * N + n) * K;
    int js[K];
#pragma unroll
    for (int t = 0; t < K; t++) js[t] = irow[t];
    float m = -CUDART_INF_F;
#pragma unroll
    for (int t = 0; t < K; t++) {
        float h = yb[(size_t)js[t] * O + o] + uu;
        h = h * gs + bv;
        h = h >= 0.f ? h : 0.2f * h;
        m = fmaxf(m, h);
    }
    out_cn[((size_t)b * Ctot + coff + o) * N + n] = m;
    if (out_nc) out_nc[((size_t)b * N + n) * Ctot + coff + o] = m;
    if (DO_NORM) {
        float sq = m * m;
#pragma unroll
        for (int off = 16; off > 0; off >>= 1)
            sq += __shfl_xor_sync(0xffffffffu, sq, off);
        int warp = o >> 5, lane = o & 31;
        if (lane == 0) s2[warp] = sq;
        __syncthreads();
        if (o == 0) {
            float s = s2[0];
            for (int w = 1; w < (O >> 5); w++) s += s2[w];
            normOut[b * N + n] = s;
        }
    }
}

__global__ void build_xm_kernel(const float* __restrict__ ft_nc, const int* __restrict__ fpsidx,
                                const int* __restrict__ idxA, float* __restrict__ xm,
                                float* __restrict__ normOut) {
    __shared__ float s2[4];
    int c = threadIdx.x;
    int m = blockIdx.x;
    int b = blockIdx.y;
    const float* fb = ft_nc + (size_t)b * N1 * 128;
    int j = fpsidx[b * M1 + m];
    float v1 = fb[(size_t)j * 128 + c];
    xm[((size_t)b * 256 + c) * M1 + m] = v1;
    const int* ir = idxA + ((size_t)b * M1 + m) * KK1;
    float mx = -CUDART_INF_F;
#pragma unroll
    for (int t = 0; t < KK1; t++) {
        int jj = ir[t];
        mx = fmaxf(mx, fb[(size_t)jj * 128 + c]);
    }
    xm[((size_t)b * 256 + 128 + c) * M1 + m] = mx;
    float sq = v1 * v1 + mx * mx;
#pragma unroll
    for (int off = 16; off > 0; off >>= 1)
        sq += __shfl_xor_sync(0xffffffffu, sq, off);
    int warp = c >> 5, lane = c & 31;
    if (lane == 0) s2[warp] = sq;
    __syncthreads();
    if (c == 0) normOut[b * M1 + m] = s2[0] + s2[1] + s2[2] + s2[3];
}

__global__ void head_kernel(const unsigned* __restrict__ venc,
                            const float* __restrict__ Wl1, const float* __restrict__ g6,
                            const float* __restrict__ b6, const float* __restrict__ Wl2,
                            const float* __restrict__ bl2, const float* __restrict__ g7,
                            const float* __restrict__ b7, const float* __restrict__ Wl3,
                            const float* __restrict__ bl3, float* __restrict__ out) {
    __shared__ float sv[2048];
    __shared__ float sh1[512];
    __shared__ float sh2[256];
    int b = blockIdx.x, tid = threadIdx.x;
    int w = tid >> 5, lane = tid & 31;
    for (int c = tid; c < 2048; c += 256) sv[c] = fdec(venc[b * 2048 + c]);
    __syncthreads();
    for (int o = w; o < 512; o += 8) {
        const float4* wr = (const float4*)(Wl1 + (size_t)o * 2048);
        float acc = 0.f;
#pragma unroll
        for (int j = 0; j < 16; j++) {
            float4 wv = wr[j * 32 + lane];
            const float4 s = *(const float4*)&sv[j * 128 + lane * 4];
            acc += wv.x * s.x + wv.y * s.y + wv.z * s.z + wv.w * s.w;
        }
#pragma unroll
        for (int off = 16; off > 0; off >>= 1)
            acc += __shfl_xor_sync(0xffffffffu, acc, off);
        if (lane == 0) {
            float h = acc * (g6[o] * BN_SCALE) + b6[o];
            sh1[o] = h >= 0.f ? h : 0.2f * h;
        }
    }
    __syncthreads();
    for (int o = w; o < 256; o += 8) {
        const float4* wr = (const float4*)(Wl2 + (size_t)o * 512);
        float acc = 0.f;
#pragma unroll
        for (int j = 0; j < 4; j++) {
            float4 wv = wr[j * 32 + lane];
            const float4 s = *(const float4*)&sh1[j * 128 + lane * 4];
            acc += wv.x * s.x + wv.y * s.y + wv.z * s.z + wv.w * s.w;
        }
#pragma unroll
        for (int off = 16; off > 0; off >>= 1)
            acc += __shfl_xor_sync(0xffffffffu, acc, off);
        if (lane == 0) {
            float h = (acc + bl2[o]) * (g7[o] * BN_SCALE) + b7[o];
            sh2[o] = h >= 0.f ? h : 0.2f * h;
        }
    }
    __syncthreads();
    for (int o = w; o < 40; o += 8) {
        const float4* wr = (const float4*)(Wl3 + (size_t)o * 256);
        float acc = 0.f;
#pragma unroll
        for (int j = 0; j < 2; j++) {
            float4 wv = wr[j * 32 + lane];
            const float4 s = *(const float4*)&sh2[j * 128 + lane * 4];
            acc += wv.x * s.x + wv.y * s.y + wv.z * s.z + wv.w * s.w;
        }
#pragma unroll
        for (int off = 16; off > 0; off >>= 1)
            acc += __shfl_xor_sync(0xffffffffu, acc, off);
        if (lane == 0) out[b * 40 + o] = acc + bl3[o];
    }
}

// ---------------- launch ----------------
extern "C" void kernel_launch(void* const* d_in, const int* in_sizes, int n_in,
                              void* d_out, int out_size) {
    const float* x   = (const float*)d_in[0];
    const float* W1  = (const float*)d_in[1];
    const float* g1  = (const float*)d_in[2];
    const float* b1  = (const float*)d_in[3];
    const float* W2  = (const float*)d_in[4];
    const float* g2  = (const float*)d_in[5];
    const float* b2  = (const float*)d_in[6];
    const float* W2m = (const float*)d_in[7];
    const float* g2m = (const float*)d_in[8];
    const float* b2m = (const float*)d_in[9];
    const float* W3  = (const float*)d_in[10];
    const float* g3  = (const float*)d_in[11];
    const float* b3  = (const float*)d_in[12];
    const float* W4  = (const float*)d_in[13];
    const float* g4  = (const float*)d_in[14];
    const float* b4  = (const float*)d_in[15];
    const float* W5  = (const float*)d_in[16];
    const float* g5  = (const float*)d_in[17];
    const float* b5  = (const float*)d_in[18];
    const float* Wl1 = (const float*)d_in[19];
    const float* g6  = (const float*)d_in[20];
    const float* b6  = (const float*)d_in[21];
    const float* Wl2 = (const float*)d_in[22];
    const float* bl2 = (const float*)d_in[23];
    const float* g7  = (const float*)d_in[24];
    const float* b7  = (const float*)d_in[25];
    const float* Wl3 = (const float*)d_in[26];
    const float* bl3 = (const float*)d_in[27];
    float* out = (float*)d_out;

    static float *pD = nullptr, *pP, *pNA, *pY, *pU, *pXt1cn, *pXt1nc,
                 *pNode1, *pXm, *pX34,
                 *pWd1, *pWu1, *pWd2, *pWu2, *pWd3, *pWu3, *pWd4, *pWu4, *pWt1, *pWt2;
    static unsigned *pVenc;
    static int *pIdx1, *pIdx2, *pIdxA, *pIdx3, *pIdx4, *pFps;
    if (!pD) {
        cudaGetSymbolAddress((void**)&pD, g_D);
        cudaGetSymbolAddress((void**)&pP, g_P);
        cudaGetSymbolAddress((void**)&pNA, g_normA);
        cudaGetSymbolAddress((void**)&pY, g_y);
        cudaGetSymbolAddress((void**)&pU, g_u);
        cudaGetSymbolAddress((void**)&pXt1cn, g_xt1_cn);
        cudaGetSymbolAddress((void**)&pXt1nc, g_xt1_nc);
        cudaGetSymbolAddress((void**)&pVenc, g_venc);
        cudaGetSymbolAddress((void**)&pNode1, g_node1);
        cudaGetSymbolAddress((void**)&pXm, g_xm);
        cudaGetSymbolAddress((void**)&pX34, g_x34);
        cudaGetSymbolAddress((void**)&pWd1, g_Wd1);
        cudaGetSymbolAddress((void**)&pWu1, g_Wu1);
        cudaGetSymbolAddress((void**)&pWd2, g_Wd2);
        cudaGetSymbolAddress((void**)&pWu2, g_Wu2);
        cudaGetSymbolAddress((void**)&pWd3, g_Wd3);
        cudaGetSymbolAddress((void**)&pWu3, g_Wu3);
        cudaGetSymbolAddress((void**)&pWd4, g_Wd4);
        cudaGetSymbolAddress((void**)&pWu4, g_Wu4);
        cudaGetSymbolAddress((void**)&pWt1, g_Wt1);
        cudaGetSymbolAddress((void**)&pWt2, g_Wt2);
        cudaGetSymbolAddress((void**)&pIdx1, g_idx1);
        cudaGetSymbolAddress((void**)&pIdx2, g_idx2);
        cudaGetSymbolAddress((void**)&pIdxA, g_idxA);
        cudaGetSymbolAddress((void**)&pIdx3, g_idx3);
        cudaGetSymbolAddress((void**)&pIdx4, g_idx4);
        cudaGetSymbolAddress((void**)&pFps, g_fpsidx);
    }

    // K1: knn1 + fps + weight preps + initv
    start_kernel<<<5209, 256>>>(x, W1, W2, W3, W4, W2m, W5, pIdx1, pFps, pNode1, out + 320,
                                pWd1, pWu1, pWd2, pWu2, pWd3, pWu3, pWd4, pWu4,
                                pWt1, pWt2, pVenc);
    // K2: econv1 direct (+ norms of x1)
    econv1_kernel<<<dim3(N1, BB), 64>>>(x, pWd1, pWu1, pIdx1, g1, b1,
                                        pXt1cn, pXt1nc, pNA);
    // K3: knn2 negdist + dual2 + aggregate knn
    mid2_kernel<<<2816, 256>>>(pXt1cn, pNA, pD, pWd2, pWu2, pY, pU, pNode1, x, pIdxA);
    // K4: topk2 (pure, zero smem, float4, group-gated)
    topk_d4_kernel<16, KK1><<<2048, 256>>>(pD, N1, N1, pIdx2);
    // K5: econv2
    econv_kernel<KK1, 0><<<dim3(N1, BB), 64>>>(pY, pU, pIdx2, 64, N1, g2, b2,
                                               pXt1cn, 128, 64, pXt1nc, nullptr);
    // K6: build xm (+ norms)
    build_xm_kernel<<<dim3(M1, BB), 128>>>(pXt1nc, pFps, pIdxA, pXm, pNA);
    // K7: knn3 negdist + maxv1 full
    nd3max_kernel<<<1152, 256>>>(pXm, pNA, pD, pWt1, pXt1cn, g2m, b2m, pVenc);
    // K8: topk3 + y3 + u3
    tk3_kernel<<<640, 256>>>(pD, pIdx3, pWd3, pWu3, pXm, pY, pU);
    // K9: econv3 (+ norms of x3)
    econv_kernel<KK2, 1><<<dim3(M1, BB), 256>>>(pY, pU, pIdx3, 256, M1, g3, b3,
                                                pX34, 512, 0, nullptr, pNA);
    // K10: knn4 negdist + y4 + u4 + maxv2a
    fusedA_kernel<<<512, 256>>>(pX34, pNA, pD, pWd4, pWu4, pY, pU, pWt2, pP);
    // K11: topk4
    topk_d4_kernel<4, KK2><<<512, 256>>>(pD, M1, M1, pIdx4);
    // K12: econv4
    econv_kernel<KK2, 0><<<dim3(M1, BB), 256>>>(pY, pU, pIdx4, 256, M1, g4, b4,
                                                pX34, 512, 256, nullptr, nullptr);
    // K13: maxv2b
    maxv2b_kernel<<<256, 256>>>(pWt2, pX34, g5, b5, pVenc, pP);
    // K14: head
    head_kernel<<<BB, 256>>>(pVenc, Wl1, g6, b6, Wl2, bl2, g7, b7, Wl3, bl3, out);
}

// round 15
// speedup vs baseline: 1.5676x; 1.5676x over previous
#include <cuda_runtime.h>
#include <math_constants.h>

#define BN_SCALE 0.9999950000374997f

#define BB 8
#define N1 2048
#define M1 512
#define KK1 20
#define KK2 10

// ---------------- scratch ----------------
__device__ float g_D[(size_t)BB * N1 * N1];
__device__ float g_P[BB * 1024 * M1];
__device__ float g_normA[BB * N1];
__device__ int   g_idx1[BB * N1 * KK1];
__device__ int   g_idx2[BB * N1 * KK1];
__device__ int   g_idxA[BB * M1 * KK1];
__device__ int   g_idx3[BB * M1 * KK2];
__device__ int   g_idx4[BB * M1 * KK2];
__device__ float g_y[BB * 131072];
__device__ float g_u[BB * 131072];
__device__ float g_xt1_cn[BB * 128 * N1];
__device__ float g_xt1_nc[BB * N1 * 128];
__device__ unsigned g_venc[BB * 2048];
__device__ int   g_fpsidx[BB * M1];
__device__ float g_node1[BB * 3 * M1];
__device__ float g_xm[BB * 256 * M1];
__device__ float g_x34[BB * 512 * M1];
__device__ float g_Wd1[64 * 3],    g_Wu1[64 * 3];
__device__ float g_Wd2[64 * 64],   g_Wu2[64 * 64];
__device__ float g_Wd3[256 * 256], g_Wu3[256 * 256];
__device__ float g_Wd4[256 * 256], g_Wu4[256 * 256];
__device__ float g_Wt1[128 * 1024];
__device__ float g_Wt2[512 * 1024];

__device__ __forceinline__ unsigned fenc(float f) {
    unsigned u = __float_as_uint(f);
    return (u & 0x80000000u) ? ~u : (u | 0x80000000u);
}
__device__ __forceinline__ float fdec(unsigned u) {
    return __uint_as_float((u & 0x80000000u) ? (u & 0x7fffffffu) : ~u);
}

__device__ __forceinline__ bool tk_better(float a, int ia, float b, int ib) {
    return a > b || (a == b && ia < ib);
}

// Sorted-insert with STRICT > (per-lane scan order is monotonic in index)
#define TK_INSERT(cv, ci)                                             \
    if ((cv) > bv3) {                                                 \
        if ((cv) > bv0) {                                             \
            bv3 = bv2; bi3 = bi2; bv2 = bv1; bi2 = bi1;               \
            bv1 = bv0; bi1 = bi0; bv0 = (cv); bi0 = (ci);             \
        } else if ((cv) > bv1) {                                      \
            bv3 = bv2; bi3 = bi2; bv2 = bv1; bi2 = bi1;               \
            bv1 = (cv); bi1 = (ci);                                   \
        } else if ((cv) > bv2) {                                      \
            bv3 = bv2; bi3 = bi2; bv2 = (cv); bi2 = (ci);             \
        } else {                                                      \
            bv3 = (cv); bi3 = (ci);                                   \
        }                                                             \
    }

// ---------------- streaming warp top-k: scalar functor source ----------------
template <int NPL, int KSEL, typename F>
__device__ __forceinline__ void warp_topk_f(const F& getv, int lane, int* __restrict__ orow) {
    unsigned long long zap = 0ull;
    float bv0, bv1, bv2, bv3;
    int bi0, bi1, bi2, bi3;

#define TK_RESET()                                                    \
    bv0 = bv1 = bv2 = bv3 = -CUDART_INF_F;                            \
    bi0 = bi1 = bi2 = bi3 = 1 << 30;

#define TK_SCAN_FIRST()                                               \
    {                                                                 \
        TK_RESET()                                                    \
        _Pragma("unroll")                                             \
        for (int s = 0; s < NPL; s++) {                               \
            float cv = getv(s);                                       \
            int ci = s * 32 + lane;                                   \
            TK_INSERT(cv, ci)                                         \
        }                                                             \
    }

#define TK_SCAN()                                                     \
    {                                                                 \
        TK_RESET()                                                    \
        _Pragma("unroll")                                             \
        for (int s = 0; s < NPL; s++) {                               \
            if ((zap >> s) & 1ull) continue;                          \
            float cv = getv(s);                                       \
            int ci = s * 32 + lane;                                   \
            TK_INSERT(cv, ci)                                         \
        }                                                             \
    }

    TK_SCAN_FIRST()
    for (int r = 0; r < KSEL; r++) {
        if (bi0 == (1 << 30)) { TK_SCAN() }
        float wb = bv0; int wi = bi0;
#pragma unroll
        for (int off = 16; off > 0; off >>= 1) {
            float ov = __shfl_xor_sync(0xffffffffu, wb, off);
            int oi = __shfl_xor_sync(0xffffffffu, wi, off);
            if (tk_better(ov, oi, wb, wi)) { wb = ov; wi = oi; }
        }
        if (lane == 0) orow[r] = wi;
        if ((wi & 31) == lane) {
            zap |= 1ull << (wi >> 5);
            bv0 = bv1; bi0 = bi1;
            bv1 = bv2; bi1 = bi2;
            bv2 = bv3; bi2 = bi3;
            bv3 = -CUDART_INF_F; bi3 = 1 << 30;
        }
    }
#undef TK_SCAN
#undef TK_SCAN_FIRST
#undef TK_RESET
}

// ---------------- streaming warp top-k: float4 D-row source ----------------
template <int NCHUNK, int KSEL>
__device__ __forceinline__ void warp_topk_d4(const float4* __restrict__ drow4, int lane,
                                             int* __restrict__ orow) {
    unsigned long long zap = 0ull;
    float bv0, bv1, bv2, bv3;
    int bi0, bi1, bi2, bi3;

#define TK_RESET()                                                    \
    bv0 = bv1 = bv2 = bv3 = -CUDART_INF_F;                            \
    bi0 = bi1 = bi2 = bi3 = 1 << 30;

#define TK_SCAN_D4_FIRST()                                            \
    {                                                                 \
        TK_RESET()                                                    \
        _Pragma("unroll 4")                                           \
        for (int c = 0; c < NCHUNK; c++) {                            \
            float4 f = drow4[c * 32 + lane];                          \
            float vals[4] = {f.x, f.y, f.z, f.w};                     \
            _Pragma("unroll")                                         \
            for (int q = 0; q < 4; q++) {                             \
                float cv = vals[q];                                   \
                int ci = c * 128 + lane * 4 + q;                      \
                TK_INSERT(cv, ci)                                     \
            }                                                         \
        }                                                             \
    }

#define TK_SCAN_D4()                                                  \
    {                                                                 \
        TK_RESET()                                                    \
        _Pragma("unroll 4")                                           \
        for (int c = 0; c < NCHUNK; c++) {                            \
            float4 f = drow4[c * 32 + lane];                          \
            float vals[4] = {f.x, f.y, f.z, f.w};                     \
            _Pragma("unroll")                                         \
            for (int q = 0; q < 4; q++) {                             \
                int s = c * 4 + q;                                    \
                if ((zap >> s) & 1ull) continue;                      \
                float cv = vals[q];                                   \
                int ci = c * 128 + lane * 4 + q;                      \
                TK_INSERT(cv, ci)                                     \
            }                                                         \
        }                                                             \
    }

    TK_SCAN_D4_FIRST()
    for (int r = 0; r < KSEL; r++) {
        if (bi0 == (1 << 30)) { TK_SCAN_D4() }
        float wb = bv0; int wi = bi0;
#pragma unroll
        for (int off = 16; off > 0; off >>= 1) {
            float ov = __shfl_xor_sync(0xffffffffu, wb, off);
            int oi = __shfl_xor_sync(0xffffffffu, wi, off);
            if (tk_better(ov, oi, wb, wi)) { wb = ov; wi = oi; }
        }
        if (lane == 0) orow[r] = wi;
        if (((wi >> 2) & 31) == lane) {
            int c = wi >> 7, q = wi & 3;
            zap |= 1ull << (c * 4 + q);
            bv0 = bv1; bi0 = bi1;
            bv1 = bv2; bi1 = bi2;
            bv2 = bv3; bi2 = bi3;
            bv3 = -CUDART_INF_F; bi3 = 1 << 30;
        }
    }
#undef TK_SCAN_D4
#undef TK_SCAN_D4_FIRST
#undef TK_RESET
}

// ---------------- shared-memory structs ----------------
struct SmemStart {
    float a[N1], b[N1], c[N1], d[N1];
    float wv[2][8];
    int wi[2][8];
    int sIdx[M1];
};
struct SmemG {
    float As[2][8][128];
    float Bs[2][8][128];
};
struct SmemDual {
    float Wds[16][65];
    float Wus[16][65];
    float Xs[16][65];
};
// mid2 is register-bound at 2 blocks/SM (regs=127), so a 33KB union is free
union SmemMid2 { SmemG g; SmemDual d; SmemStart k; };

// ---------------- small bodies ----------------
__device__ void prepw_body(const float* __restrict__ W, float* __restrict__ WdT,
                           float* __restrict__ WuT, int O, int C, int vb) {
    int i = vb * 256 + threadIdx.x;
    if (i >= O * C) return;
    int o = i / C, c = i % C;
    float wd = W[o * 2 * C + c];
    float wc = W[o * 2 * C + C + c];
    WdT[(size_t)c * O + o] = wd;
    WuT[(size_t)c * O + o] = wc - wd;
}

__device__ void wtrans_body(const float* __restrict__ W, float* __restrict__ Wt,
                            int O, int C, int vb) {
    int i = vb * 256 + threadIdx.x;
    if (i >= O * C) return;
    int o = i / C, c = i % C;
    Wt[(size_t)c * O + o] = W[(size_t)o * C + c];
}

__device__ void initv_body(unsigned* venc, int vb) {
    int i = vb * 256 + threadIdx.x;
    if (i < BB * 2048) venc[i] = 0u;
}

template <int KSEL>
__device__ void knn3d_body(const float* __restrict__ Q, const float* __restrict__ P,
                           int M, int* __restrict__ idxOut, long qbs, long pbs,
                           int mBase, int b, SmemStart& S) {
    int tid = threadIdx.x;
    int nt = blockDim.x;
    const float* Pb = P + (size_t)b * pbs;
    for (int j = tid; j < N1; j += nt) {
        float vx = Pb[j], vy = Pb[N1 + j], vz = Pb[2 * N1 + j];
        S.a[j] = vx; S.b[j] = vy; S.c[j] = vz;
        S.d[j] = __fadd_rn(__fadd_rn(__fmul_rn(vx, vx), __fmul_rn(vy, vy)),
                           __fmul_rn(vz, vz));
    }
    __syncthreads();
    int warp = tid >> 5, lane = tid & 31;
    int m = mBase + warp;
    const float* Qb = Q + (size_t)b * qbs;
    float qx = Qb[m], qy = Qb[M + m], qz = Qb[2 * M + m];
    auto getv = [&](int s) {
        int j = s * 32 + lane;
        float inner = fmaf(qx, S.a[j], fmaf(qy, S.b[j], qz * S.c[j]));
        return 2.f * inner - S.d[j];
    };
    warp_topk_f<64, KSEL>(getv, lane, idxOut + ((size_t)b * M + m) * KSEL);
}

__device__ void fps_body(const float* __restrict__ xyz, int* __restrict__ fpsidx,
                         float* __restrict__ node1, float* __restrict__ outNode,
                         int b, SmemStart& S) {
    int tid = threadIdx.x;
    int warp = tid >> 5, lane = tid & 31;
    const float* xb = xyz + (size_t)b * 3 * N1;
    for (int j = tid; j < N1; j += 256) {
        S.a[j] = xb[j];
        S.b[j] = xb[N1 + j];
        S.c[j] = xb[2 * N1 + j];
        S.d[j] = 1e10f;
    }
    __syncthreads();
    int last = 0;
    for (int it = 0; it < M1; it++) {
        int par = it & 1;
        if (tid == 0) { S.sIdx[it] = last; fpsidx[b * M1 + it] = last; }
        float px = S.a[last], py = S.b[last], pz = S.c[last];
        float bmax = -CUDART_INF_F;
        int bidx = 0;
#pragma unroll
        for (int r = 0; r < 8; r++) {
            int j = tid + r * 256;
            float dx = __fsub_rn(S.a[j], px);
            float dy = __fsub_rn(S.b[j], py);
            float dz = __fsub_rn(S.c[j], pz);
            float dd = __fadd_rn(__fadd_rn(__fmul_rn(dx, dx), __fmul_rn(dy, dy)),
                                 __fmul_rn(dz, dz));
            float nd = fminf(S.d[j], dd);
            S.d[j] = nd;
            if (nd > bmax) { bmax = nd; bidx = j; }
        }
#pragma unroll
        for (int off = 16; off > 0; off >>= 1) {
            float ov = __shfl_xor_sync(0xffffffffu, bmax, off);
            int oi = __shfl_xor_sync(0xffffffffu, bidx, off);
            if (ov > bmax || (ov == bmax && oi < bidx)) { bmax = ov; bidx = oi; }
        }
        if (lane == 0) { S.wv[par][warp] = bmax; S.wi[par][warp] = bidx; }
        __syncthreads();
        float bv = S.wv[par][0];
        int bi = S.wi[par][0];
#pragma unroll
        for (int w = 1; w < 8; w++) {
            float ov = S.wv[par][w];
            int oi = S.wi[par][w];
            if (ov > bv || (ov == bv && oi < bi)) { bv = ov; bi = oi; }
        }
        last = bi;
    }
    __syncthreads();
    for (int m = tid; m < M1; m += 256) {
        int j = S.sIdx[m];
        float vx = S.a[j], vy = S.b[j], vz = S.c[j];
        node1[((size_t)b * 3 + 0) * M1 + m] = vx;
        node1[((size_t)b * 3 + 1) * M1 + m] = vy;
        node1[((size_t)b * 3 + 2) * M1 + m] = vz;
        outNode[((size_t)b * 3 + 0) * M1 + m] = vx;
        outNode[((size_t)b * 3 + 1) * M1 + m] = vy;
        outNode[((size_t)b * 3 + 2) * M1 + m] = vz;
    }
}

__device__ void gemm_dual_body(const float* __restrict__ WdT, const float* __restrict__ WuT,
                               const float* __restrict__ X,
                               float* __restrict__ y, float* __restrict__ u,
                               int O, int C, int N, long xbs,
                               int bx, int by, int bz, SmemDual& S) {
    int o0 = by * 64, n0 = bx * 64;
    int t = threadIdx.x;
    int tx = t & 15, ty = t >> 4;
    const float* Xb = X + (size_t)bz * xbs;
    float accd[4][4], accu[4][4];
#pragma unroll
    for (int i = 0; i < 4; i++)
#pragma unroll
        for (int j = 0; j < 4; j++) { accd[i][j] = 0.f; accu[i][j] = 0.f; }

    for (int c0 = 0; c0 < C; c0 += 16) {
#pragma unroll
        for (int l = 0; l < 4; l++) {
            int e = t + l * 256;
            int wo = e & 63, wc = e >> 6;
            float vd = 0.f, vu = 0.f;
            if (o0 + wo < O && c0 + wc < C) {
                vd = WdT[(size_t)(c0 + wc) * O + o0 + wo];
                vu = WuT[(size_t)(c0 + wc) * O + o0 + wo];
            }
            S.Wds[wc][wo] = vd;
            S.Wus[wc][wo] = vu;
            float xv = 0.f;
            if (c0 + wc < C && n0 + wo < N) xv = Xb[(size_t)(c0 + wc) * N + n0 + wo];
            S.Xs[wc][wo] = xv;
        }
        __syncthreads();
#pragma unroll
        for (int kk = 0; kk < 16; kk++) {
            float wd[4], wu[4], xv[4];
#pragma unroll
            for (int i = 0; i < 4; i++) { wd[i] = S.Wds[kk][ty + 16 * i]; wu[i] = S.Wus[kk][ty + 16 * i]; }
#pragma unroll
            for (int j = 0; j < 4; j++) xv[j] = S.Xs[kk][tx + 16 * j];
#pragma unroll
            for (int i = 0; i < 4; i++)
#pragma unroll
                for (int j = 0; j < 4; j++) {
                    accd[i][j] += wd[i] * xv[j];
                    accu[i][j] += wu[i] * xv[j];
                }
        }
        __syncthreads();
    }
#pragma unroll
    for (int i = 0; i < 4; i++) {
        int o = o0 + ty + 16 * i;
        if (o >= O) continue;
#pragma unroll
        for (int j = 0; j < 4; j++) {
            int n = n0 + tx + 16 * j;
            if (n >= N) continue;
            y[((size_t)bz * N + n) * O + o] = accd[i][j];
            u[((size_t)bz * N + n) * O + o] = accu[i][j];
        }
    }
}

// ================= 128x128x8 GEMM body =================
template <int MODE>
__device__ void gemm128_body(
    const float* __restrict__ A, const float* __restrict__ B, float* __restrict__ out,
    int M, int N, int C, long ldA, long ldB, long abs_, long bbs,
    const float* __restrict__ p1, const float* __restrict__ p2,
    unsigned* __restrict__ venc, int voff, int ldOut,
    float* __restrict__ P, int ldP,
    int bx, int by, int bz, SmemG& S) {
    int m0 = by * 128, n0 = bx * 128;
    int t = threadIdx.x;
    int tx = t & 15, ty = t >> 4;
    int lr = t >> 5;
    int lc = (t & 31) * 4;
    const float* aSrc = A + (size_t)bz * abs_ + (size_t)lr * ldA + m0 + lc;
    const float* bSrc = B + (size_t)bz * bbs + (size_t)lr * ldB + n0 + lc;
    float acc[8][8];
#pragma unroll
    for (int i = 0; i < 8; i++)
#pragma unroll
        for (int j = 0; j < 8; j++) acc[i][j] = 0.f;

    int nc = C >> 3;
    float4 av = *(const float4*)aSrc;
    float4 bv = *(const float4*)bSrc;
    *(float4*)&S.As[0][lr][lc] = av;
    *(float4*)&S.Bs[0][lr][lc] = bv;
    __syncthreads();
    int p = 0;
    for (int i = 0; i < nc; i++) {
        if (i + 1 < nc) {
            av = *(const float4*)(aSrc + (size_t)(i + 1) * 8 * ldA);
            bv = *(const float4*)(bSrc + (size_t)(i + 1) * 8 * ldB);
        }
#pragma unroll
        for (int k = 0; k < 8; k++) {
            float4 a0 = *(float4*)&S.As[p][k][ty * 4];
            float4 a1 = *(float4*)&S.As[p][k][64 + ty * 4];
            float4 b0 = *(float4*)&S.Bs[p][k][tx * 4];
            float4 b1 = *(float4*)&S.Bs[p][k][64 + tx * 4];
            float aa[8] = {a0.x, a0.y, a0.z, a0.w, a1.x, a1.y, a1.z, a1.w};
            float bb[8] = {b0.x, b0.y, b0.z, b0.w, b1.x, b1.y, b1.z, b1.w};
#pragma unroll
            for (int ii = 0; ii < 8; ii++)
#pragma unroll
                for (int jj = 0; jj < 8; jj++) acc[ii][jj] += aa[ii] * bb[jj];
        }
        if (i + 1 < nc) {
            *(float4*)&S.As[p ^ 1][lr][lc] = av;
            *(float4*)&S.Bs[p ^ 1][lr][lc] = bv;
            __syncthreads();
            p ^= 1;
        }
    }

    if (MODE == 0) {
#pragma unroll
        for (int i = 0; i < 8; i++) {
            int m = m0 + (i < 4 ? ty * 4 + i : 64 + ty * 4 + i - 4);
            float nq = p1[bz * M + m];
            float* orow = out + ((size_t)bz * M + m) * ldOut;
            float4 d0, d1;
            d0.x = 2.f * acc[i][0] - nq - p2[bz * N + n0 + tx * 4 + 0];
            d0.y = 2.f * acc[i][1] - nq - p2[bz * N + n0 + tx * 4 + 1];
            d0.z = 2.f * acc[i][2] - nq - p2[bz * N + n0 + tx * 4 + 2];
            d0.w = 2.f * acc[i][3] - nq - p2[bz * N + n0 + tx * 4 + 3];
            d1.x = 2.f * acc[i][4] - nq - p2[bz * N + n0 + 64 + tx * 4 + 0];
            d1.y = 2.f * acc[i][5] - nq - p2[bz * N + n0 + 64 + tx * 4 + 1];
            d1.z = 2.f * acc[i][6] - nq - p2[bz * N + n0 + 64 + tx * 4 + 2];
            d1.w = 2.f * acc[i][7] - nq - p2[bz * N + n0 + 64 + tx * 4 + 3];
            *(float4*)&orow[n0 + tx * 4] = d0;
            *(float4*)&orow[n0 + 64 + tx * 4] = d1;
        }
    } else if (MODE == 1 || MODE == 5) {
        if (MODE == 5) {
#pragma unroll
            for (int i = 0; i < 8; i++) {
                int m = m0 + (i < 4 ? ty * 4 + i : 64 + ty * 4 + i - 4);
                const float* prow = P + ((size_t)bz * M + m) * ldP;
                float4 q0 = *(const float4*)&prow[n0 + tx * 4];
                float4 q1 = *(const float4*)&prow[n0 + 64 + tx * 4];
                acc[i][0] += q0.x; acc[i][1] += q0.y; acc[i][2] += q0.z; acc[i][3] += q0.w;
                acc[i][4] += q1.x; acc[i][5] += q1.y; acc[i][6] += q1.z; acc[i][7] += q1.w;
            }
        }
#pragma unroll
        for (int i = 0; i < 8; i++) {
            int m = m0 + (i < 4 ? ty * 4 + i : 64 + ty * 4 + i - 4);
            float gs = p1[m] * BN_SCALE, bvv = p2[m];
            float mx = -CUDART_INF_F;
#pragma unroll
            for (int j = 0; j < 8; j++) {
                float h = acc[i][j] * gs + bvv;
                h = h >= 0.f ? h : 0.2f * h;
                mx = fmaxf(mx, h);
            }
#pragma unroll
            for (int off = 8; off > 0; off >>= 1)
                mx = fmaxf(mx, __shfl_xor_sync(0xffffffffu, mx, off));
            if (tx == 0) atomicMax(&venc[bz * 2048 + voff + m], fenc(mx));
        }
    } else if (MODE == 4) {
#pragma unroll
        for (int i = 0; i < 8; i++) {
            int m = m0 + (i < 4 ? ty * 4 + i : 64 + ty * 4 + i - 4);
            float* prow = P + ((size_t)bz * M + m) * ldP;
            float4 v0, v1;
            v0.x = acc[i][0]; v0.y = acc[i][1]; v0.z = acc[i][2]; v0.w = acc[i][3];
            v1.x = acc[i][4]; v1.y = acc[i][5]; v1.z = acc[i][6]; v1.w = acc[i][7];
            *(float4*)&prow[n0 + tx * 4] = v0;
            *(float4*)&prow[n0 + 64 + tx * 4] = v1;
        }
    } else {
#pragma unroll
        for (int jj = 0; jj < 8; jj++) {
            int n = n0 + (jj < 4 ? tx * 4 + jj : 64 + tx * 4 + jj - 4);
            float* orow = out + ((size_t)bz * N + n) * ldOut;
            float4 v0, v1;
            v0.x = acc[0][jj]; v0.y = acc[1][jj]; v0.z = acc[2][jj]; v0.w = acc[3][jj];
            v1.x = acc[4][jj]; v1.y = acc[5][jj]; v1.z = acc[6][jj]; v1.w = acc[7][jj];
            *(float4*)&orow[m0 + ty * 4] = v0;
            *(float4*)&orow[m0 + 64 + ty * 4] = v1;
        }
    }
}

// ---------------- dispatcher kernels ----------------
__global__ __launch_bounds__(256) void start_kernel(
    const float* __restrict__ x,
    const float* __restrict__ W1, const float* __restrict__ W2,
    const float* __restrict__ W3, const float* __restrict__ W4,
    const float* __restrict__ W2m, const float* __restrict__ W5,
    int* __restrict__ idx1, int* __restrict__ fpsidx,
    float* __restrict__ node1, float* __restrict__ outNode,
    float* Wd1, float* Wu1, float* Wd2, float* Wu2,
    float* Wd3, float* Wu3, float* Wd4, float* Wu4,
    float* Wt1, float* Wt2, unsigned* venc) {
    __shared__ SmemStart S;
    int blk = blockIdx.x;
    if (blk < 2048) {
        knn3d_body<KK1>(x, x, N1, idx1, 3L * N1, 3L * N1, (blk & 255) * 8, blk >> 8, S);
    } else if (blk < 2056) {
        fps_body(x, fpsidx, node1, outNode, blk - 2048, S);
    } else if (blk < 2057) {
        prepw_body(W1, Wd1, Wu1, 64, 3, blk - 2056);
    } else if (blk < 2073) {
        prepw_body(W2, Wd2, Wu2, 64, 64, blk - 2057);
    } else if (blk < 2329) {
        prepw_body(W3, Wd3, Wu3, 256, 256, blk - 2073);
    } else if (blk < 2585) {
        prepw_body(W4, Wd4, Wu4, 256, 256, blk - 2329);
    } else if (blk < 3097) {
        wtrans_body(W2m, Wt1, 1024, 128, blk - 2585);
    } else if (blk < 5145) {
        wtrans_body(W5, Wt2, 1024, 512, blk - 3097);
    } else {
        initv_body(venc, blk - 5145);
    }
}

// econv1 direct from coords
__global__ __launch_bounds__(64) void econv1_kernel(
    const float* __restrict__ x, const float* __restrict__ Wd1T, const float* __restrict__ Wu1T,
    const int* __restrict__ idx, const float* __restrict__ g, const float* __restrict__ bb,
    float* __restrict__ out_cn, float* __restrict__ out_nc, float* __restrict__ normOut) {
    __shared__ float sjx[KK1], sjy[KK1], sjz[KK1];
    __shared__ int sidx[KK1];
    __shared__ float s2[2];
    int o = threadIdx.x;
    int n = blockIdx.x;
    int b = blockIdx.y;
    const float* xb = x + (size_t)b * 3 * N1;
    if (o < KK1) sidx[o] = idx[((size_t)b * N1 + n) * KK1 + o];
    __syncthreads();
    if (o < KK1) {
        int j = sidx[o];
        sjx[o] = xb[j];
        sjy[o] = xb[N1 + j];
        sjz[o] = xb[2 * N1 + j];
    }
    __syncthreads();
    float wdx = Wd1T[o], wdy = Wd1T[64 + o], wdz = Wd1T[128 + o];
    float wux = Wu1T[o], wuy = Wu1T[64 + o], wuz = Wu1T[128 + o];
    float xn = xb[n], yn = xb[N1 + n], zn = xb[2 * N1 + n];
    float uu = wux * xn + wuy * yn + wuz * zn;
    float gs = g[o] * BN_SCALE, bv = bb[o];
    float m = -CUDART_INF_F;
#pragma unroll
    for (int t = 0; t < KK1; t++) {
        float h = wdx * sjx[t] + wdy * sjy[t] + wdz * sjz[t] + uu;
        h = h * gs + bv;
        h = h >= 0.f ? h : 0.2f * h;
        m = fmaxf(m, h);
    }
    out_cn[((size_t)b * 128 + o) * N1 + n] = m;
    out_nc[((size_t)b * N1 + n) * 128 + o] = m;
    float sq = m * m;
#pragma unroll
    for (int off = 16; off > 0; off >>= 1)
        sq += __shfl_xor_sync(0xffffffffu, sq, off);
    int warp = o >> 5, lane = o & 31;
    if (lane == 0) s2[warp] = sq;
    __syncthreads();
    if (o == 0) normOut[b * N1 + n] = s2[0] + s2[1];
}

// knn2 negdist (2048) + dual2 (256) + aggregate knn (512)
__global__ __launch_bounds__(256) void mid2_kernel(
    const float* __restrict__ xt1cn, const float* __restrict__ normA, float* __restrict__ D,
    const float* __restrict__ Wd2, const float* __restrict__ Wu2,
    float* __restrict__ y, float* __restrict__ u,
    const float* __restrict__ node1, const float* __restrict__ x, int* __restrict__ idxA) {
    __shared__ SmemMid2 S;
    int blk = blockIdx.x;
    if (blk < 2048) {
        gemm128_body<0>(xt1cn, xt1cn, D, N1, N1, 64, N1, N1, 128L * N1, 128L * N1,
                        normA, normA, nullptr, 0, N1, nullptr, 0,
                        blk & 15, (blk >> 4) & 15, blk >> 8, S.g);
    } else if (blk < 2304) {
        int i = blk - 2048;
        gemm_dual_body(Wd2, Wu2, xt1cn, y, u, 64, 64, N1, 128L * N1, i & 31, 0, i >> 5, S.d);
    } else {
        int i = blk - 2304;
        knn3d_body<KK1>(node1, x, M1, idxA, 3L * M1, 3L * N1, (i & 63) * 8, i >> 6, S.k);
    }
}

// pure float4 top-k from D (zero smem, occupancy-capped regs: measured 45 regs -> 4 blocks/SM fits)
template <int NCHUNK, int KSEL>
__global__ __launch_bounds__(256, 4) void topk_d4_kernel(
    const float* __restrict__ D, int rows, int N, int* __restrict__ idxOut) {
    int wid = blockIdx.x * 8 + (threadIdx.x >> 5);
    int lane = threadIdx.x & 31;
    if (wid >= BB * rows) return;
    const float4* drow4 = (const float4*)(D + (size_t)wid * N);
    warp_topk_d4<NCHUNK, KSEL>(drow4, lane, idxOut + (size_t)wid * KSEL);
}

// negdist3 (128) + maxv1 full C=128 (1024)
__global__ __launch_bounds__(256) void nd3max_kernel(
    const float* __restrict__ xm, const float* __restrict__ normA, float* __restrict__ D,
    const float* __restrict__ Wt1, const float* __restrict__ xt1cn,
    const float* __restrict__ g2m, const float* __restrict__ b2m,
    unsigned* __restrict__ venc) {
    __shared__ SmemG S;
    int blk = blockIdx.x;
    if (blk < 128) {
        gemm128_body<0>(xm, xm, D, M1, M1, 256, M1, M1, 256L * M1, 256L * M1,
                        normA, normA, nullptr, 0, M1, nullptr, 0,
                        blk & 3, (blk >> 2) & 3, blk >> 4, S);
    } else {
        int i = blk - 128;
        gemm128_body<1>(Wt1, xt1cn, nullptr, 1024, N1, 128, 1024, N1, 0, 128L * N1,
                        g2m, b2m, venc, 0, 0, nullptr, 0,
                        i & 15, (i >> 4) & 7, i >> 7, S);
    }
}

// topk3 (512) + y3 (64) + u3 (64)
__global__ __launch_bounds__(256) void tk3_kernel(
    const float* __restrict__ D, int* __restrict__ idx3,
    const float* __restrict__ Wd3, const float* __restrict__ Wu3,
    const float* __restrict__ xm, float* __restrict__ y, float* __restrict__ u) {
    __shared__ SmemG S;
    int blk = blockIdx.x;
    if (blk < 512) {
        int wid = blk * 8 + (threadIdx.x >> 5);
        int lane = threadIdx.x & 31;
        const float4* drow4 = (const float4*)(D + (size_t)wid * M1);
        warp_topk_d4<4, KK2>(drow4, lane, idx3 + (size_t)wid * KK2);
    } else if (blk < 576) {
        int i = blk - 512;
        gemm128_body<2>(Wd3, xm, y, 256, M1, 256, 256, M1, 0, 256L * M1,
                        nullptr, nullptr, nullptr, 0, 256, nullptr, 0,
                        i & 3, (i >> 2) & 1, i >> 3, S);
    } else {
        int i = blk - 576;
        gemm128_body<2>(Wu3, xm, u, 256, M1, 256, 256, M1, 0, 256L * M1,
                        nullptr, nullptr, nullptr, 0, 256, nullptr, 0,
                        i & 3, (i >> 2) & 1, i >> 3, S);
    }
}

// negdist4 (128) + y4 (64) + u4 (64) + maxv2a partial (256)
__global__ __launch_bounds__(256) void fusedA_kernel(
    const float* __restrict__ x34, const float* __restrict__ normA, float* __restrict__ D,
    const float* __restrict__ Wd4, const float* __restrict__ Wu4,
    float* __restrict__ y, float* __restrict__ u,
    const float* __restrict__ Wt2, float* __restrict__ P) {
    __shared__ SmemG S;
    int blk = blockIdx.x;
    if (blk < 128) {
        gemm128_body<0>(x34, x34, D, M1, M1, 256, M1, M1, 512L * M1, 512L * M1,
                        normA, normA, nullptr, 0, M1, nullptr, 0,
                        blk & 3, (blk >> 2) & 3, blk >> 4, S);
    } else if (blk < 192) {
        int i = blk - 128;
        gemm128_body<2>(Wd4, x34, y, 256, M1, 256, 256, M1, 0, 512L * M1,
                        nullptr, nullptr, nullptr, 0, 256, nullptr, 0,
                        i & 3, (i >> 2) & 1, i >> 3, S);
    } else if (blk < 256) {
        int i = blk - 192;
        gemm128_body<2>(Wu4, x34, u, 256, M1, 256, 256, M1, 0, 512L * M1,
                        nullptr, nullptr, nullptr, 0, 256, nullptr, 0,
                        i & 3, (i >> 2) & 1, i >> 3, S);
    } else {
        int i = blk - 256;
        gemm128_body<4>(Wt2, x34, nullptr, 1024, M1, 256, 1024, M1, 0, 512L * M1,
                        nullptr, nullptr, nullptr, 0, 0, P, M1,
                        i & 3, (i >> 2) & 7, i >> 5, S);
    }
}

// maxv2 final
__global__ __launch_bounds__(256) void maxv2b_kernel(
    const float* __restrict__ Wt2, const float* __restrict__ x34,
    const float* __restrict__ g5, const float* __restrict__ b5,
    unsigned* __restrict__ venc, float* __restrict__ P) {
    __shared__ SmemG S;
    int blk = blockIdx.x;
    gemm128_body<5>(Wt2 + 256 * 1024, x34 + 256L * M1, nullptr, 1024, M1, 256, 1024, M1,
                    0, 512L * M1, g5, b5, venc, 1024, 0, P, M1,
                    blk & 3, (blk >> 2) & 7, blk >> 5, S);
}

// ---------------- edge conv epilogue (layers 2..4) ----------------
template <int K, int DO_NORM>
__global__ void econv_kernel(const float* __restrict__ y, const float* __restrict__ u,
                             const int* __restrict__ idx, int O, int N,
                             const float* __restrict__ g, const float* __restrict__ bb,
                             float* __restrict__ out_cn, int Ctot, int coff,
                             float* __restrict__ out_nc, float* __restrict__ normOut) {
    __shared__ float s2[8];
    int o = threadIdx.x;
    int n = blockIdx.x;
    int b = blockIdx.y;
    const float* yb = y + (size_t)b * N * O;
    float uu = u[((size_t)b * N + n) * O + o];
    float gs = g[o] * BN_SCALE, bv = bb[o];
    const int* irow = idx + ((size_t)b * N + n) * K;
    int js[K];
#pragma unroll
    for (int t = 0; t < K; t++) js[t] = irow[t];
    float m = -CUDART_INF_F;
#pragma unroll
    for (int t = 0; t < K; t++) {
        float h = yb[(size_t)js[t] * O + o] + uu;
        h = h * gs + bv;
        h = h >= 0.f ? h : 0.2f * h;
        m = fmaxf(m, h);
    }
    out_cn[((size_t)b * Ctot + coff + o) * N + n] = m;
    if (out_nc) out_nc[((size_t)b * N + n) * Ctot + coff + o] = m;
    if (DO_NORM) {
        float sq = m * m;
#pragma unroll
        for (int off = 16; off > 0; off >>= 1)
            sq += __shfl_xor_sync(0xffffffffu, sq, off);
        int warp = o >> 5, lane = o & 31;
        if (lane == 0) s2[warp] = sq;
        __syncthreads();
        if (o == 0) {
            float s = s2[0];
            for (int w = 1; w < (O >> 5); w++) s += s2[w];
            normOut[b * N + n] = s;
        }
    }
}

__global__ void build_xm_kernel(const float* __restrict__ ft_nc, const int* __restrict__ fpsidx,
                                const int* __restrict__ idxA, float* __restrict__ xm,
                                float* __restrict__ normOut) {
    __shared__ float s2[4];
    int c = threadIdx.x;
    int m = blockIdx.x;
    int b = blockIdx.y;
    const float* fb = ft_nc + (size_t)b * N1 * 128;
    int j = fpsidx[b * M1 + m];
    float v1 = fb[(size_t)j * 128 + c];
    xm[((size_t)b * 256 + c) * M1 + m] = v1;
    const int* ir = idxA + ((size_t)b * M1 + m) * KK1;
    float mx = -CUDART_INF_F;
#pragma unroll
    for (int t = 0; t < KK1; t++) {
        int jj = ir[t];
        mx = fmaxf(mx, fb[(size_t)jj * 128 + c]);
    }
    xm[((size_t)b * 256 + 128 + c) * M1 + m] = mx;
    float sq = v1 * v1 + mx * mx;
#pragma unroll
    for (int off = 16; off > 0; off >>= 1)
        sq += __shfl_xor_sync(0xffffffffu, sq, off);
    int warp = c >> 5, lane = c & 31;
    if (lane == 0) s2[warp] = sq;
    __syncthreads();
    if (c == 0) normOut[b * M1 + m] = s2[0] + s2[1] + s2[2] + s2[3];
}

__global__ void head_kernel(const unsigned* __restrict__ venc,
                            const float* __restrict__ Wl1, const float* __restrict__ g6,
                            const float* __restrict__ b6, const float* __restrict__ Wl2,
                            const float* __restrict__ bl2, const float* __restrict__ g7,
                            const float* __restrict__ b7, const float* __restrict__ Wl3,
                            const float* __restrict__ bl3, float* __restrict__ out) {
    __shared__ float sv[2048];
    __shared__ float sh1[512];
    __shared__ float sh2[256];
    int b = blockIdx.x, tid = threadIdx.x;
    int w = tid >> 5, lane = tid & 31;
    for (int c = tid; c < 2048; c += 256) sv[c] = fdec(venc[b * 2048 + c]);
    __syncthreads();
    for (int o = w; o < 512; o += 8) {
        const float4* wr = (const float4*)(Wl1 + (size_t)o * 2048);
        float acc = 0.f;
#pragma unroll
        for (int j = 0; j < 16; j++) {
            float4 wv = wr[j * 32 + lane];
            const float4 s = *(const float4*)&sv[j * 128 + lane * 4];
            acc += wv.x * s.x + wv.y * s.y + wv.z * s.z + wv.w * s.w;
        }
#pragma unroll
        for (int off = 16; off > 0; off >>= 1)
            acc += __shfl_xor_sync(0xffffffffu, acc, off);
        if (lane == 0) {
            float h = acc * (g6[o] * BN_SCALE) + b6[o];
            sh1[o] = h >= 0.f ? h : 0.2f * h;
        }
    }
    __syncthreads();
    for (int o = w; o < 256; o += 8) {
        const float4* wr = (const float4*)(Wl2 + (size_t)o * 512);
        float acc = 0.f;
#pragma unroll
        for (int j = 0; j < 4; j++) {
            float4 wv = wr[j * 32 + lane];
            const float4 s = *(const float4*)&sh1[j * 128 + lane * 4];
            acc += wv.x * s.x + wv.y * s.y + wv.z * s.z + wv.w * s.w;
        }
#pragma unroll
        for (int off = 16; off > 0; off >>= 1)
            acc += __shfl_xor_sync(0xffffffffu, acc, off);
        if (lane == 0) {
            float h = (acc + bl2[o]) * (g7[o] * BN_SCALE) + b7[o];
            sh2[o] = h >= 0.f ? h : 0.2f * h;
        }
    }
    __syncthreads();
    for (int o = w; o < 40; o += 8) {
        const float4* wr = (const float4*)(Wl3 + (size_t)o * 256);
        float acc = 0.f;
#pragma unroll
        for (int j = 0; j < 2; j++) {
            float4 wv = wr[j * 32 + lane];
            const float4 s = *(const float4*)&sh2[j * 128 + lane * 4];
            acc += wv.x * s.x + wv.y * s.y + wv.z * s.z + wv.w * s.w;
        }
#pragma unroll
        for (int off = 16; off > 0; off >>= 1)
            acc += __shfl_xor_sync(0xffffffffu, acc, off);
        if (lane == 0) out[b * 40 + o] = acc + bl3[o];
    }
}

// ---------------- launch ----------------
extern "C" void kernel_launch(void* const* d_in, const int* in_sizes, int n_in,
                              void* d_out, int out_size) {
    const float* x   = (const float*)d_in[0];
    const float* W1  = (const float*)d_in[1];
    const float* g1  = (const float*)d_in[2];
    const float* b1  = (const float*)d_in[3];
    const float* W2  = (const float*)d_in[4];
    const float* g2  = (const float*)d_in[5];
    const float* b2  = (const float*)d_in[6];
    const float* W2m = (const float*)d_in[7];
    const float* g2m = (const float*)d_in[8];
    const float* b2m = (const float*)d_in[9];
    const float* W3  = (const float*)d_in[10];
    const float* g3  = (const float*)d_in[11];
    const float* b3  = (const float*)d_in[12];
    const float* W4  = (const float*)d_in[13];
    const float* g4  = (const float*)d_in[14];
    const float* b4  = (const float*)d_in[15];
    const float* W5  = (const float*)d_in[16];
    const float* g5  = (const float*)d_in[17];
    const float* b5  = (const float*)d_in[18];
    const float* Wl1 = (const float*)d_in[19];
    const float* g6  = (const float*)d_in[20];
    const float* b6  = (const float*)d_in[21];
    const float* Wl2 = (const float*)d_in[22];
    const float* bl2 = (const float*)d_in[23];
    const float* g7  = (const float*)d_in[24];
    const float* b7  = (const float*)d_in[25];
    const float* Wl3 = (const float*)d_in[26];
    const float* bl3 = (const float*)d_in[27];
    float* out = (float*)d_out;

    static float *pD = nullptr, *pP, *pNA, *pY, *pU, *pXt1cn, *pXt1nc,
                 *pNode1, *pXm, *pX34,
                 *pWd1, *pWu1, *pWd2, *pWu2, *pWd3, *pWu3, *pWd4, *pWu4, *pWt1, *pWt2;
    static unsigned *pVenc;
    static int *pIdx1, *pIdx2, *pIdxA, *pIdx3, *pIdx4, *pFps;
    if (!pD) {
        cudaGetSymbolAddress((void**)&pD, g_D);
        cudaGetSymbolAddress((void**)&pP, g_P);
        cudaGetSymbolAddress((void**)&pNA, g_normA);
        cudaGetSymbolAddress((void**)&pY, g_y);
        cudaGetSymbolAddress((void**)&pU, g_u);
        cudaGetSymbolAddress((void**)&pXt1cn, g_xt1_cn);
        cudaGetSymbolAddress((void**)&pXt1nc, g_xt1_nc);
        cudaGetSymbolAddress((void**)&pVenc, g_venc);
        cudaGetSymbolAddress((void**)&pNode1, g_node1);
        cudaGetSymbolAddress((void**)&pXm, g_xm);
        cudaGetSymbolAddress((void**)&pX34, g_x34);
        cudaGetSymbolAddress((void**)&pWd1, g_Wd1);
        cudaGetSymbolAddress((void**)&pWu1, g_Wu1);
        cudaGetSymbolAddress((void**)&pWd2, g_Wd2);
        cudaGetSymbolAddress((void**)&pWu2, g_Wu2);
        cudaGetSymbolAddress((void**)&pWd3, g_Wd3);
        cudaGetSymbolAddress((void**)&pWu3, g_Wu3);
        cudaGetSymbolAddress((void**)&pWd4, g_Wd4);
        cudaGetSymbolAddress((void**)&pWu4, g_Wu4);
        cudaGetSymbolAddress((void**)&pWt1, g_Wt1);
        cudaGetSymbolAddress((void**)&pWt2, g_Wt2);
        cudaGetSymbolAddress((void**)&pIdx1, g_idx1);
        cudaGetSymbolAddress((void**)&pIdx2, g_idx2);
        cudaGetSymbolAddress((void**)&pIdxA, g_idxA);
        cudaGetSymbolAddress((void**)&pIdx3, g_idx3);
        cudaGetSymbolAddress((void**)&pIdx4, g_idx4);
        cudaGetSymbolAddress((void**)&pFps, g_fpsidx);
    }

    // K1: knn1 + fps + weight preps + initv
    start_kernel<<<5209, 256>>>(x, W1, W2, W3, W4, W2m, W5, pIdx1, pFps, pNode1, out + 320,
                                pWd1, pWu1, pWd2, pWu2, pWd3, pWu3, pWd4, pWu4,
                                pWt1, pWt2, pVenc);
    // K2: econv1 direct (+ norms of x1)
    econv1_kernel<<<dim3(N1, BB), 64>>>(x, pWd1, pWu1, pIdx1, g1, b1,
                                        pXt1cn, pXt1nc, pNA);
    // K3: knn2 negdist + dual2 + aggregate knn
    mid2_kernel<<<2816, 256>>>(pXt1cn, pNA, pD, pWd2, pWu2, pY, pU, pNode1, x, pIdxA);
    // K4: topk2 (pure, zero smem, float4)
    topk_d4_kernel<16, KK1><<<2048, 256>>>(pD, N1, N1, pIdx2);
    // K5: econv2
    econv_kernel<KK1, 0><<<dim3(N1, BB), 64>>>(pY, pU, pIdx2, 64, N1, g2, b2,
                                               pXt1cn, 128, 64, pXt1nc, nullptr);
    // K6: build xm (+ norms)
    build_xm_kernel<<<dim3(M1, BB), 128>>>(pXt1nc, pFps, pIdxA, pXm, pNA);
    // K7: knn3 negdist + maxv1 full
    nd3max_kernel<<<1152, 256>>>(pXm, pNA, pD, pWt1, pXt1cn, g2m, b2m, pVenc);
    // K8: topk3 + y3 + u3
    tk3_kernel<<<640, 256>>>(pD, pIdx3, pWd3, pWu3, pXm, pY, pU);
    // K9: econv3 (+ norms of x3)
    econv_kernel<KK2, 1><<<dim3(M1, BB), 256>>>(pY, pU, pIdx3, 256, M1, g3, b3,
                                                pX34, 512, 0, nullptr, pNA);
    // K10: knn4 negdist + y4 + u4 + maxv2a
    fusedA_kernel<<<512, 256>>>(pX34, pNA, pD, pWd4, pWu4, pY, pU, pWt2, pP);
    // K11: topk4
    topk_d4_kernel<4, KK2><<<512, 256>>>(pD, M1, M1, pIdx4);
    // K12: econv4
    econv_kernel<KK2, 0><<<dim3(M1, BB), 256>>>(pY, pU, pIdx4, 256, M1, g4, b4,
                                                pX34, 512, 256, nullptr, nullptr);
    // K13: maxv2b
    maxv2b_kernel<<<256, 256>>>(pWt2, pX34, g5, b5, pVenc, pP);
    // K14: head
    head_kernel<<<BB, 256>>>(pVenc, Wl1, g6, b6, Wl2, bl2, g7, b7, Wl3, bl3, out);
}

// round 16
// speedup vs baseline: 1.5929x; 1.0161x over previous
#include <cuda_runtime.h>
#include <math_constants.h>

#define BN_SCALE 0.9999950000374997f

#define BB 8
#define N1 2048
#define M1 512
#define KK1 20
#define KK2 10

// ---------------- scratch ----------------
__device__ float g_D[(size_t)BB * N1 * N1];
__device__ float g_P[BB * 1024 * M1];
__device__ float g_normA[BB * N1];
__device__ int   g_idxA[BB * M1 * KK1];
__device__ int   g_idx3[BB * M1 * KK2];
__device__ int   g_idx4[BB * M1 * KK2];
__device__ float g_y[BB * 131072];
__device__ float g_u[BB * 131072];
__device__ float g_xt1_cn[BB * 128 * N1];
__device__ float g_xt1_nc[BB * N1 * 128];
__device__ unsigned g_venc[BB * 2048];
__device__ int   g_fpsidx[BB * M1];
__device__ float g_node1[BB * 3 * M1];
__device__ float g_xm[BB * 256 * M1];
__device__ float g_x34[BB * 512 * M1];
__device__ float g_Wd2[64 * 64],   g_Wu2[64 * 64];
__device__ float g_Wd3[256 * 256], g_Wu3[256 * 256];
__device__ float g_Wd4[256 * 256], g_Wu4[256 * 256];
__device__ float g_Wt1[128 * 1024];
__device__ float g_Wt2[512 * 1024];

__device__ __forceinline__ unsigned fenc(float f) {
    unsigned u = __float_as_uint(f);
    return (u & 0x80000000u) ? ~u : (u | 0x80000000u);
}
__device__ __forceinline__ float fdec(unsigned u) {
    return __uint_as_float((u & 0x80000000u) ? (u & 0x7fffffffu) : ~u);
}

__device__ __forceinline__ bool tk_better(float a, int ia, float b, int ib) {
    return a > b || (a == b && ia < ib);
}

struct NullSink {
    __device__ __forceinline__ void operator()(int, int) const {}
};

// Sorted-insert with STRICT > (per-lane scan order is monotonic in index)
#define TK_INSERT(cv, ci)                                             \
    if ((cv) > bv3) {                                                 \
        if ((cv) > bv0) {                                             \
            bv3 = bv2; bi3 = bi2; bv2 = bv1; bi2 = bi1;               \
            bv1 = bv0; bi1 = bi0; bv0 = (cv); bi0 = (ci);             \
        } else if ((cv) > bv1) {                                      \
            bv3 = bv2; bi3 = bi2; bv2 = bv1; bi2 = bi1;               \
            bv1 = (cv); bi1 = (ci);                                   \
        } else if ((cv) > bv2) {                                      \
            bv3 = bv2; bi3 = bi2; bv2 = (cv); bi2 = (ci);             \
        } else {                                                      \
            bv3 = (cv); bi3 = (ci);                                   \
        }                                                             \
    }

// ---------------- streaming warp top-k: scalar functor source + per-round sink ----------------
template <int NPL, int KSEL, typename F, typename SK>
__device__ __forceinline__ void warp_topk_f(const F& getv, int lane, int* orow,
                                            const SK& sink) {
    unsigned long long zap = 0ull;
    float bv0, bv1, bv2, bv3;
    int bi0, bi1, bi2, bi3;

#define TK_RESET()                                                    \
    bv0 = bv1 = bv2 = bv3 = -CUDART_INF_F;                            \
    bi0 = bi1 = bi2 = bi3 = 1 << 30;

#define TK_SCAN_FIRST()                                               \
    {                                                                 \
        TK_RESET()                                                    \
        _Pragma("unroll")                                             \
        for (int s = 0; s < NPL; s++) {                               \
            float cv = getv(s);                                       \
            int ci = s * 32 + lane;                                   \
            TK_INSERT(cv, ci)                                         \
        }                                                             \
    }

#define TK_SCAN()                                                     \
    {                                                                 \
        TK_RESET()                                                    \
        _Pragma("unroll")                                             \
        for (int s = 0; s < NPL; s++) {                               \
            if ((zap >> s) & 1ull) continue;                          \
            float cv = getv(s);                                       \
            int ci = s * 32 + lane;                                   \
            TK_INSERT(cv, ci)                                         \
        }                                                             \
    }

    TK_SCAN_FIRST()
    for (int r = 0; r < KSEL; r++) {
        if (bi0 == (1 << 30)) { TK_SCAN() }
        float wb = bv0; int wi = bi0;
#pragma unroll
        for (int off = 16; off > 0; off >>= 1) {
            float ov = __shfl_xor_sync(0xffffffffu, wb, off);
            int oi = __shfl_xor_sync(0xffffffffu, wi, off);
            if (tk_better(ov, oi, wb, wi)) { wb = ov; wi = oi; }
        }
        if (orow && lane == 0) orow[r] = wi;
        sink(r, wi);
        if ((wi & 31) == lane) {
            zap |= 1ull << (wi >> 5);
            bv0 = bv1; bi0 = bi1;
            bv1 = bv2; bi1 = bi2;
            bv2 = bv3; bi2 = bi3;
            bv3 = -CUDART_INF_F; bi3 = 1 << 30;
        }
    }
#undef TK_SCAN
#undef TK_SCAN_FIRST
#undef TK_RESET
}

template <int NPL, int KSEL, typename F>
__device__ __forceinline__ void warp_topk_f(const F& getv, int lane, int* orow) {
    warp_topk_f<NPL, KSEL>(getv, lane, orow, NullSink{});
}

// ---------------- streaming warp top-k: float4 D-row source + per-round sink ----------------
template <int NCHUNK, int KSEL, typename SK>
__device__ __forceinline__ void warp_topk_d4(const float4* __restrict__ drow4, int lane,
                                             int* orow, const SK& sink) {
    unsigned long long zap = 0ull;
    float bv0, bv1, bv2, bv3;
    int bi0, bi1, bi2, bi3;

#define TK_RESET()                                                    \
    bv0 = bv1 = bv2 = bv3 = -CUDART_INF_F;                            \
    bi0 = bi1 = bi2 = bi3 = 1 << 30;

#define TK_SCAN_D4_FIRST()                                            \
    {                                                                 \
        TK_RESET()                                                    \
        _Pragma("unroll 4")                                           \
        for (int c = 0; c < NCHUNK; c++) {                            \
            float4 f = drow4[c * 32 + lane];                          \
            float vals[4] = {f.x, f.y, f.z, f.w};                     \
            _Pragma("unroll")                                         \
            for (int q = 0; q < 4; q++) {                             \
                float cv = vals[q];                                   \
                int ci = c * 128 + lane * 4 + q;                      \
                TK_INSERT(cv, ci)                                     \
            }                                                         \
        }                                                             \
    }

#define TK_SCAN_D4()                                                  \
    {                                                                 \
        TK_RESET()                                                    \
        _Pragma("unroll 4")                                           \
        for (int c = 0; c < NCHUNK; c++) {                            \
            float4 f = drow4[c * 32 + lane];                          \
            float vals[4] = {f.x, f.y, f.z, f.w};                     \
            _Pragma("unroll")                                         \
            for (int q = 0; q < 4; q++) {                             \
                int s = c * 4 + q;                                    \
                if ((zap >> s) & 1ull) continue;                      \
                float cv = vals[q];                                   \
                int ci = c * 128 + lane * 4 + q;                      \
                TK_INSERT(cv, ci)                                     \
            }                                                         \
        }                                                             \
    }

    TK_SCAN_D4_FIRST()
    for (int r = 0; r < KSEL; r++) {
        if (bi0 == (1 << 30)) { TK_SCAN_D4() }
        float wb = bv0; int wi = bi0;
#pragma unroll
        for (int off = 16; off > 0; off >>= 1) {
            float ov = __shfl_xor_sync(0xffffffffu, wb, off);
            int oi = __shfl_xor_sync(0xffffffffu, wi, off);
            if (tk_better(ov, oi, wb, wi)) { wb = ov; wi = oi; }
        }
        if (orow && lane == 0) orow[r] = wi;
        sink(r, wi);
        if (((wi >> 2) & 31) == lane) {
            int c = wi >> 7, q = wi & 3;
            zap |= 1ull << (c * 4 + q);
            bv0 = bv1; bi0 = bi1;
            bv1 = bv2; bi1 = bi2;
            bv2 = bv3; bi2 = bi3;
            bv3 = -CUDART_INF_F; bi3 = 1 << 30;
        }
    }
#undef TK_SCAN_D4
#undef TK_SCAN_D4_FIRST
#undef TK_RESET
}

template <int NCHUNK, int KSEL>
__device__ __forceinline__ void warp_topk_d4(const float4* __restrict__ drow4, int lane,
                                             int* orow) {
    warp_topk_d4<NCHUNK, KSEL>(drow4, lane, orow, NullSink{});
}

// ---------------- shared-memory structs ----------------
struct SmemStart {
    float a[N1], b[N1], c[N1], d[N1];
    float wv[2][8];
    int wi[2][8];
    int sIdx[M1];
};
struct SmemG {
    float As[2][8][128];
    float Bs[2][8][128];
};
struct SmemDual {
    float Wds[16][65];
    float Wus[16][65];
    float Xs[16][65];
};
union SmemMid2 { SmemG g; SmemDual d; SmemStart k; };

// ---------------- small bodies ----------------
__device__ void prepw_body(const float* __restrict__ W, float* __restrict__ WdT,
                           float* __restrict__ WuT, int O, int C, int vb) {
    int i = vb * 256 + threadIdx.x;
    if (i >= O * C) return;
    int o = i / C, c = i % C;
    float wd = W[o * 2 * C + c];
    float wc = W[o * 2 * C + C + c];
    WdT[(size_t)c * O + o] = wd;
    WuT[(size_t)c * O + o] = wc - wd;
}

__device__ void wtrans_body(const float* __restrict__ W, float* __restrict__ Wt,
                            int O, int C, int vb) {
    int i = vb * 256 + threadIdx.x;
    if (i >= O * C) return;
    int o = i / C, c = i % C;
    Wt[(size_t)c * O + o] = W[(size_t)o * C + c];
}

__device__ void initv_body(unsigned* venc, int vb) {
    int i = vb * 256 + threadIdx.x;
    if (i < BB * 2048) venc[i] = 0u;
}

// plain kNN (C=3) for aggregate
template <int KSEL>
__device__ void knn3d_body(const float* __restrict__ Q, const float* __restrict__ P,
                           int M, int* __restrict__ idxOut, long qbs, long pbs,
                           int mBase, int b, SmemStart& S) {
    int tid = threadIdx.x;
    int nt = blockDim.x;
    const float* Pb = P + (size_t)b * pbs;
    for (int j = tid; j < N1; j += nt) {
        float vx = Pb[j], vy = Pb[N1 + j], vz = Pb[2 * N1 + j];
        S.a[j] = vx; S.b[j] = vy; S.c[j] = vz;
        S.d[j] = __fadd_rn(__fadd_rn(__fmul_rn(vx, vx), __fmul_rn(vy, vy)),
                           __fmul_rn(vz, vz));
    }
    __syncthreads();
    int warp = tid >> 5, lane = tid & 31;
    int m = mBase + warp;
    const float* Qb = Q + (size_t)b * qbs;
    float qx = Qb[m], qy = Qb[M + m], qz = Qb[2 * M + m];
    auto getv = [&](int s) {
        int j = s * 32 + lane;
        float inner = fmaf(qx, S.a[j], fmaf(qy, S.b[j], qz * S.c[j]));
        return 2.f * inner - S.d[j];
    };
    warp_topk_f<64, KSEL>(getv, lane, idxOut + ((size_t)b * M + m) * KSEL);
}

// fused knn1 + econv1: per winner, all lanes update 2 channels (o=lane, o+32)
__device__ void knn1_econv_body(const float* __restrict__ x, const float* __restrict__ W1,
                                const float* __restrict__ g1, const float* __restrict__ b1,
                                float* __restrict__ out_cn, float* __restrict__ out_nc,
                                float* __restrict__ normOut,
                                int mBase, int b, SmemStart& S) {
    int tid = threadIdx.x;
    int nt = blockDim.x;
    const float* Pb = x + (size_t)b * 3 * N1;
    for (int j = tid; j < N1; j += nt) {
        float vx = Pb[j], vy = Pb[N1 + j], vz = Pb[2 * N1 + j];
        S.a[j] = vx; S.b[j] = vy; S.c[j] = vz;
        S.d[j] = __fadd_rn(__fadd_rn(__fmul_rn(vx, vx), __fmul_rn(vy, vy)),
                           __fmul_rn(vz, vz));
    }
    __syncthreads();
    int warp = tid >> 5, lane = tid & 31;
    int n = mBase + warp;
    float qx = Pb[n], qy = Pb[N1 + n], qz = Pb[2 * N1 + n];
    // channel weights: o0 = lane, o1 = lane + 32; W1 is [64][6] row-major
    int o0 = lane, o1 = lane + 32;
    float wd00 = W1[o0 * 6 + 0], wd01 = W1[o0 * 6 + 1], wd02 = W1[o0 * 6 + 2];
    float wu00 = W1[o0 * 6 + 3] - wd00, wu01 = W1[o0 * 6 + 4] - wd01, wu02 = W1[o0 * 6 + 5] - wd02;
    float wd10 = W1[o1 * 6 + 0], wd11 = W1[o1 * 6 + 1], wd12 = W1[o1 * 6 + 2];
    float wu10 = W1[o1 * 6 + 3] - wd10, wu11 = W1[o1 * 6 + 4] - wd11, wu12 = W1[o1 * 6 + 5] - wd12;
    float uu0 = wu00 * qx + wu01 * qy + wu02 * qz;
    float uu1 = wu10 * qx + wu11 * qy + wu12 * qz;
    float gs0 = g1[o0] * BN_SCALE, bvv0 = b1[o0];
    float gs1 = g1[o1] * BN_SCALE, bvv1 = b1[o1];
    float m0 = -CUDART_INF_F, m1 = -CUDART_INF_F;
    auto getv = [&](int s) {
        int j = s * 32 + lane;
        float inner = fmaf(qx, S.a[j], fmaf(qy, S.b[j], qz * S.c[j]));
        return 2.f * inner - S.d[j];
    };
    auto sink = [&](int r, int wi) {
        float jx = S.a[wi], jy = S.b[wi], jz = S.c[wi];
        float h0 = wd00 * jx + wd01 * jy + wd02 * jz + uu0;
        h0 = h0 * gs0 + bvv0;
        h0 = h0 >= 0.f ? h0 : 0.2f * h0;
        m0 = fmaxf(m0, h0);
        float h1 = wd10 * jx + wd11 * jy + wd12 * jz + uu1;
        h1 = h1 * gs1 + bvv1;
        h1 = h1 >= 0.f ? h1 : 0.2f * h1;
        m1 = fmaxf(m1, h1);
    };
    warp_topk_f<64, KK1>(getv, lane, (int*)nullptr, sink);
    out_cn[((size_t)b * 128 + o0) * N1 + n] = m0;
    out_cn[((size_t)b * 128 + o1) * N1 + n] = m1;
    out_nc[((size_t)b * N1 + n) * 128 + o0] = m0;
    out_nc[((size_t)b * N1 + n) * 128 + o1] = m1;
    float sq = m0 * m0 + m1 * m1;
#pragma unroll
    for (int off = 16; off > 0; off >>= 1)
        sq += __shfl_xor_sync(0xffffffffu, sq, off);
    if (lane == 0) normOut[b * N1 + n] = sq;
}

__device__ void fps_body(const float* __restrict__ xyz, int* __restrict__ fpsidx,
                         float* __restrict__ node1, float* __restrict__ outNode,
                         int b, SmemStart& S) {
    int tid = threadIdx.x;
    int warp = tid >> 5, lane = tid & 31;
    const float* xb = xyz + (size_t)b * 3 * N1;
    for (int j = tid; j < N1; j += 256) {
        S.a[j] = xb[j];
        S.b[j] = xb[N1 + j];
        S.c[j] = xb[2 * N1 + j];
        S.d[j] = 1e10f;
    }
    __syncthreads();
    int last = 0;
    for (int it = 0; it < M1; it++) {
        int par = it & 1;
        if (tid == 0) { S.sIdx[it] = last; fpsidx[b * M1 + it] = last; }
        float px = S.a[last], py = S.b[last], pz = S.c[last];
        float bmax = -CUDART_INF_F;
        int bidx = 0;
#pragma unroll
        for (int r = 0; r < 8; r++) {
            int j = tid + r * 256;
            float dx = __fsub_rn(S.a[j], px);
            float dy = __fsub_rn(S.b[j], py);
            float dz = __fsub_rn(S.c[j], pz);
            float dd = __fadd_rn(__fadd_rn(__fmul_rn(dx, dx), __fmul_rn(dy, dy)),
                                 __fmul_rn(dz, dz));
            float nd = fminf(S.d[j], dd);
            S.d[j] = nd;
            if (nd > bmax) { bmax = nd; bidx = j; }
        }
#pragma unroll
        for (int off = 16; off > 0; off >>= 1) {
            float ov = __shfl_xor_sync(0xffffffffu, bmax, off);
            int oi = __shfl_xor_sync(0xffffffffu, bidx, off);
            if (ov > bmax || (ov == bmax && oi < bidx)) { bmax = ov; bidx = oi; }
        }
        if (lane == 0) { S.wv[par][warp] = bmax; S.wi[par][warp] = bidx; }
        __syncthreads();
        float bv = S.wv[par][0];
        int bi = S.wi[par][0];
#pragma unroll
        for (int w = 1; w < 8; w++) {
            float ov = S.wv[par][w];
            int oi = S.wi[par][w];
            if (ov > bv || (ov == bv && oi < bi)) { bv = ov; bi = oi; }
        }
        last = bi;
    }
    __syncthreads();
    for (int m = tid; m < M1; m += 256) {
        int j = S.sIdx[m];
        float vx = S.a[j], vy = S.b[j], vz = S.c[j];
        node1[((size_t)b * 3 + 0) * M1 + m] = vx;
        node1[((size_t)b * 3 + 1) * M1 + m] = vy;
        node1[((size_t)b * 3 + 2) * M1 + m] = vz;
        outNode[((size_t)b * 3 + 0) * M1 + m] = vx;
        outNode[((size_t)b * 3 + 1) * M1 + m] = vy;
        outNode[((size_t)b * 3 + 2) * M1 + m] = vz;
    }
}

__device__ void gemm_dual_body(const float* __restrict__ WdT, const float* __restrict__ WuT,
                               const float* __restrict__ X,
                               float* __restrict__ y, float* __restrict__ u,
                               int O, int C, int N, long xbs,
                               int bx, int by, int bz, SmemDual& S) {
    int o0 = by * 64, n0 = bx * 64;
    int t = threadIdx.x;
    int tx = t & 15, ty = t >> 4;
    const float* Xb = X + (size_t)bz * xbs;
    float accd[4][4], accu[4][4];
#pragma unroll
    for (int i = 0; i < 4; i++)
#pragma unroll
        for (int j = 0; j < 4; j++) { accd[i][j] = 0.f; accu[i][j] = 0.f; }

    for (int c0 = 0; c0 < C; c0 += 16) {
#pragma unroll
        for (int l = 0; l < 4; l++) {
            int e = t + l * 256;
            int wo = e & 63, wc = e >> 6;
            float vd = 0.f, vu = 0.f;
            if (o0 + wo < O && c0 + wc < C) {
                vd = WdT[(size_t)(c0 + wc) * O + o0 + wo];
                vu = WuT[(size_t)(c0 + wc) * O + o0 + wo];
            }
            S.Wds[wc][wo] = vd;
            S.Wus[wc][wo] = vu;
            float xv = 0.f;
            if (c0 + wc < C && n0 + wo < N) xv = Xb[(size_t)(c0 + wc) * N + n0 + wo];
            S.Xs[wc][wo] = xv;
        }
        __syncthreads();
#pragma unroll
        for (int kk = 0; kk < 16; kk++) {
            float wd[4], wu[4], xv[4];
#pragma unroll
            for (int i = 0; i < 4; i++) { wd[i] = S.Wds[kk][ty + 16 * i]; wu[i] = S.Wus[kk][ty + 16 * i]; }
#pragma unroll
            for (int j = 0; j < 4; j++) xv[j] = S.Xs[kk][tx + 16 * j];
#pragma unroll
            for (int i = 0; i < 4; i++)
#pragma unroll
                for (int j = 0; j < 4; j++) {
                    accd[i][j] += wd[i] * xv[j];
                    accu[i][j] += wu[i] * xv[j];
                }
        }
        __syncthreads();
    }
#pragma unroll
    for (int i = 0; i < 4; i++) {
        int o = o0 + ty + 16 * i;
        if (o >= O) continue;
#pragma unroll
        for (int j = 0; j < 4; j++) {
            int n = n0 + tx + 16 * j;
            if (n >= N) continue;
            y[((size_t)bz * N + n) * O + o] = accd[i][j];
            u[((size_t)bz * N + n) * O + o] = accu[i][j];
        }
    }
}

// ================= 128x128x8 GEMM body =================
template <int MODE>
__device__ void gemm128_body(
    const float* __restrict__ A, const float* __restrict__ B, float* __restrict__ out,
    int M, int N, int C, long ldA, long ldB, long abs_, long bbs,
    const float* __restrict__ p1, const float* __restrict__ p2,
    unsigned* __restrict__ venc, int voff, int ldOut,
    float* __restrict__ P, int ldP,
    int bx, int by, int bz, SmemG& S) {
    int m0 = by * 128, n0 = bx * 128;
    int t = threadIdx.x;
    int tx = t & 15, ty = t >> 4;
    int lr = t >> 5;
    int lc = (t & 31) * 4;
    const float* aSrc = A + (size_t)bz * abs_ + (size_t)lr * ldA + m0 + lc;
    const float* bSrc = B + (size_t)bz * bbs + (size_t)lr * ldB + n0 + lc;
    float acc[8][8];
#pragma unroll
    for (int i = 0; i < 8; i++)
#pragma unroll
        for (int j = 0; j < 8; j++) acc[i][j] = 0.f;

    int nc = C >> 3;
    float4 av = *(const float4*)aSrc;
    float4 bv = *(const float4*)bSrc;
    *(float4*)&S.As[0][lr][lc] = av;
    *(float4*)&S.Bs[0][lr][lc] = bv;
    __syncthreads();
    int p = 0;
    for (int i = 0; i < nc; i++) {
        if (i + 1 < nc) {
            av = *(const float4*)(aSrc + (size_t)(i + 1) * 8 * ldA);
            bv = *(const float4*)(bSrc + (size_t)(i + 1) * 8 * ldB);
        }
#pragma unroll
        for (int k = 0; k < 8; k++) {
            float4 a0 = *(float4*)&S.As[p][k][ty * 4];
            float4 a1 = *(float4*)&S.As[p][k][64 + ty * 4];
            float4 b0 = *(float4*)&S.Bs[p][k][tx * 4];
            float4 b1 = *(float4*)&S.Bs[p][k][64 + tx * 4];
            float aa[8] = {a0.x, a0.y, a0.z, a0.w, a1.x, a1.y, a1.z, a1.w};
            float bb[8] = {b0.x, b0.y, b0.z, b0.w, b1.x, b1.y, b1.z, b1.w};
#pragma unroll
            for (int ii = 0; ii < 8; ii++)
#pragma unroll
                for (int jj = 0; jj < 8; jj++) acc[ii][jj] += aa[ii] * bb[jj];
        }
        if (i + 1 < nc) {
            *(float4*)&S.As[p ^ 1][lr][lc] = av;
            *(float4*)&S.Bs[p ^ 1][lr][lc] = bv;
            __syncthreads();
            p ^= 1;
        }
    }

    if (MODE == 0) {
#pragma unroll
        for (int i = 0; i < 8; i++) {
            int m = m0 + (i < 4 ? ty * 4 + i : 64 + ty * 4 + i - 4);
            float nq = p1[bz * M + m];
            float* orow = out + ((size_t)bz * M + m) * ldOut;
            float4 d0, d1;
            d0.x = 2.f * acc[i][0] - nq - p2[bz * N + n0 + tx * 4 + 0];
            d0.y = 2.f * acc[i][1] - nq - p2[bz * N + n0 + tx * 4 + 1];
            d0.z = 2.f * acc[i][2] - nq - p2[bz * N + n0 + tx * 4 + 2];
            d0.w = 2.f * acc[i][3] - nq - p2[bz * N + n0 + tx * 4 + 3];
            d1.x = 2.f * acc[i][4] - nq - p2[bz * N + n0 + 64 + tx * 4 + 0];
            d1.y = 2.f * acc[i][5] - nq - p2[bz * N + n0 + 64 + tx * 4 + 1];
            d1.z = 2.f * acc[i][6] - nq - p2[bz * N + n0 + 64 + tx * 4 + 2];
            d1.w = 2.f * acc[i][7] - nq - p2[bz * N + n0 + 64 + tx * 4 + 3];
            *(float4*)&orow[n0 + tx * 4] = d0;
            *(float4*)&orow[n0 + 64 + tx * 4] = d1;
        }
    } else if (MODE == 1 || MODE == 5) {
        if (MODE == 5) {
#pragma unroll
            for (int i = 0; i < 8; i++) {
                int m = m0 + (i < 4 ? ty * 4 + i : 64 + ty * 4 + i - 4);
                const float* prow = P + ((size_t)bz * M + m) * ldP;
                float4 q0 = *(const float4*)&prow[n0 + tx * 4];
                float4 q1 = *(const float4*)&prow[n0 + 64 + tx * 4];
                acc[i][0] += q0.x; acc[i][1] += q0.y; acc[i][2] += q0.z; acc[i][3] += q0.w;
                acc[i][4] += q1.x; acc[i][5] += q1.y; acc[i][6] += q1.z; acc[i][7] += q1.w;
            }
        }
#pragma unroll
        for (int i = 0; i < 8; i++) {
            int m = m0 + (i < 4 ? ty * 4 + i : 64 + ty * 4 + i - 4);
            float gs = p1[m] * BN_SCALE, bvv = p2[m];
            float mx = -CUDART_INF_F;
#pragma unroll
            for (int j = 0; j < 8; j++) {
                float h = acc[i][j] * gs + bvv;
                h = h >= 0.f ? h : 0.2f * h;
                mx = fmaxf(mx, h);
            }
#pragma unroll
            for (int off = 8; off > 0; off >>= 1)
                mx = fmaxf(mx, __shfl_xor_sync(0xffffffffu, mx, off));
            if (tx == 0) atomicMax(&venc[bz * 2048 + voff + m], fenc(mx));
        }
    } else if (MODE == 4) {
#pragma unroll
        for (int i = 0; i < 8; i++) {
            int m = m0 + (i < 4 ? ty * 4 + i : 64 + ty * 4 + i - 4);
            float* prow = P + ((size_t)bz * M + m) * ldP;
            float4 v0, v1;
            v0.x = acc[i][0]; v0.y = acc[i][1]; v0.z = acc[i][2]; v0.w = acc[i][3];
            v1.x = acc[i][4]; v1.y = acc[i][5]; v1.z = acc[i][6]; v1.w = acc[i][7];
            *(float4*)&prow[n0 + tx * 4] = v0;
            *(float4*)&prow[n0 + 64 + tx * 4] = v1;
        }
    } else {
#pragma unroll
        for (int jj = 0; jj < 8; jj++) {
            int n = n0 + (jj < 4 ? tx * 4 + jj : 64 + tx * 4 + jj - 4);
            float* orow = out + ((size_t)bz * N + n) * ldOut;
            float4 v0, v1;
            v0.x = acc[0][jj]; v0.y = acc[1][jj]; v0.z = acc[2][jj]; v0.w = acc[3][jj];
            v1.x = acc[4][jj]; v1.y = acc[5][jj]; v1.z = acc[6][jj]; v1.w = acc[7][jj];
            *(float4*)&orow[m0 + ty * 4] = v0;
            *(float4*)&orow[m0 + 64 + ty * 4] = v1;
        }
    }
}

// ---------------- dispatcher kernels ----------------
__global__ __launch_bounds__(256) void start_kernel(
    const float* __restrict__ x,
    const float* __restrict__ W1, const float* __restrict__ W2,
    const float* __restrict__ W3, const float* __restrict__ W4,
    const float* __restrict__ W2m, const float* __restrict__ W5,
    const float* __restrict__ g1, const float* __restrict__ b1,
    int* __restrict__ fpsidx,
    float* __restrict__ node1, float* __restrict__ outNode,
    float* Wd2, float* Wu2,
    float* Wd3, float* Wu3, float* Wd4, float* Wu4,
    float* Wt1, float* Wt2, unsigned* venc,
    float* __restrict__ xt1cn, float* __restrict__ xt1nc, float* __restrict__ normA) {
    __shared__ SmemStart S;
    int blk = blockIdx.x;
    if (blk < 2048) {
        knn1_econv_body(x, W1, g1, b1, xt1cn, xt1nc, normA, (blk & 255) * 8, blk >> 8, S);
    } else if (blk < 2056) {
        fps_body(x, fpsidx, node1, outNode, blk - 2048, S);
    } else if (blk < 2072) {
        prepw_body(W2, Wd2, Wu2, 64, 64, blk - 2056);
    } else if (blk < 2328) {
        prepw_body(W3, Wd3, Wu3, 256, 256, blk - 2072);
    } else if (blk < 2584) {
        prepw_body(W4, Wd4, Wu4, 256, 256, blk - 2328);
    } else if (blk < 3096) {
        wtrans_body(W2m, Wt1, 1024, 128, blk - 2584);
    } else if (blk < 5144) {
        wtrans_body(W5, Wt2, 1024, 512, blk - 3096);
    } else {
        initv_body(venc, blk - 5144);
    }
}

// knn2 negdist (2048) + dual2 (256) + aggregate knn (512)
__global__ __launch_bounds__(256) void mid2_kernel(
    const float* __restrict__ xt1cn, const float* __restrict__ normA, float* __restrict__ D,
    const float* __restrict__ Wd2, const float* __restrict__ Wu2,
    float* __restrict__ y, float* __restrict__ u,
    const float* __restrict__ node1, const float* __restrict__ x, int* __restrict__ idxA) {
    __shared__ SmemMid2 S;
    int blk = blockIdx.x;
    if (blk < 2048) {
        gemm128_body<0>(xt1cn, xt1cn, D, N1, N1, 64, N1, N1, 128L * N1, 128L * N1,
                        normA, normA, nullptr, 0, N1, nullptr, 0,
                        blk & 15, (blk >> 4) & 15, blk >> 8, S.g);
    } else if (blk < 2304) {
        int i = blk - 2048;
        gemm_dual_body(Wd2, Wu2, xt1cn, y, u, 64, 64, N1, 128L * N1, i & 31, 0, i >> 5, S.d);
    } else {
        int i = blk - 2304;
        knn3d_body<KK1>(node1, x, M1, idxA, 3L * M1, 3L * N1, (i & 63) * 8, i >> 6, S.k);
    }
}

// fused topk2 + econv2: topk collects winners, tail gathers y rows (L2-resident)
__global__ __launch_bounds__(256, 3) void tk2econv_kernel(
    const float* __restrict__ D, const float* __restrict__ y, const float* __restrict__ u,
    const float* __restrict__ g2, const float* __restrict__ b2,
    float* __restrict__ out_cn, float* __restrict__ out_nc) {
    int warp = threadIdx.x >> 5, lane = threadIdx.x & 31;
    int wid = blockIdx.x * 8 + warp;
    int b = wid >> 11, n = wid & 2047;
    const float4* drow4 = (const float4*)(D + (size_t)wid * N1);
    int w[KK1];
    auto sink = [&](int r, int wi) { w[r] = wi; };
    warp_topk_d4<16, KK1>(drow4, lane, (int*)nullptr, sink);
    // econv2 tail: channels o0=lane, o1=lane+32 of layer-2 output (offset 64)
    int o0 = lane, o1 = lane + 32;
    const float* yb = y + (size_t)b * N1 * 64;
    float uu0 = u[((size_t)b * N1 + n) * 64 + o0];
    float uu1 = u[((size_t)b * N1 + n) * 64 + o1];
    float gs0 = g2[o0] * BN_SCALE, bv0 = b2[o0];
    float gs1 = g2[o1] * BN_SCALE, bv1 = b2[o1];
    float m0 = -CUDART_INF_F, m1 = -CUDART_INF_F;
#pragma unroll
    for (int r = 0; r < KK1; r++) {
        int j = w[r];
        float h0 = yb[(size_t)j * 64 + o0] + uu0;
        h0 = h0 * gs0 + bv0;
        h0 = h0 >= 0.f ? h0 : 0.2f * h0;
        m0 = fmaxf(m0, h0);
        float h1 = yb[(size_t)j * 64 + o1] + uu1;
        h1 = h1 * gs1 + bv1;
        h1 = h1 >= 0.f ? h1 : 0.2f * h1;
        m1 = fmaxf(m1, h1);
    }
    out_cn[((size_t)b * 128 + 64 + o0) * N1 + n] = m0;
    out_cn[((size_t)b * 128 + 64 + o1) * N1 + n] = m1;
    out_nc[((size_t)b * N1 + n) * 128 + 64 + o0] = m0;
    out_nc[((size_t)b * N1 + n) * 128 + 64 + o1] = m1;
}

// pure float4 top-k from D (zero smem)
template <int NCHUNK, int KSEL>
__global__ __launch_bounds__(256, 4) void topk_d4_kernel(
    const float* __restrict__ D, int rows, int N, int* __restrict__ idxOut) {
    int wid = blockIdx.x * 8 + (threadIdx.x >> 5);
    int lane = threadIdx.x & 31;
    if (wid >= BB * rows) return;
    const float4* drow4 = (const float4*)(D + (size_t)wid * N);
    warp_topk_d4<NCHUNK, KSEL>(drow4, lane, idxOut + (size_t)wid * KSEL);
}

// negdist3 (128) + maxv1 full C=128 (1024)
__global__ __launch_bounds__(256) void nd3max_kernel(
    const float* __restrict__ xm, const float* __restrict__ normA, float* __restrict__ D,
    const float* __restrict__ Wt1, const float* __restrict__ xt1cn,
    const float* __restrict__ g2m, const float* __restrict__ b2m,
    unsigned* __restrict__ venc) {
    __shared__ SmemG S;
    int blk = blockIdx.x;
    if (blk < 128) {
        gemm128_body<0>(xm, xm, D, M1, M1, 256, M1, M1, 256L * M1, 256L * M1,
                        normA, normA, nullptr, 0, M1, nullptr, 0,
                        blk & 3, (blk >> 2) & 3, blk >> 4, S);
    } else {
        int i = blk - 128;
        gemm128_body<1>(Wt1, xt1cn, nullptr, 1024, N1, 128, 1024, N1, 0, 128L * N1,
                        g2m, b2m, venc, 0, 0, nullptr, 0,
                        i & 15, (i >> 4) & 7, i >> 7, S);
    }
}

// topk3 (512) + y3 (64) + u3 (64)
__global__ __launch_bounds__(256) void tk3_kernel(
    const float* __restrict__ D, int* __restrict__ idx3,
    const float* __restrict__ Wd3, const float* __restrict__ Wu3,
    const float* __restrict__ xm, float* __restrict__ y, float* __restrict__ u) {
    __shared__ SmemG S;
    int blk = blockIdx.x;
    if (blk < 512) {
        int wid = blk * 8 + (threadIdx.x >> 5);
        int lane = threadIdx.x & 31;
        const float4* drow4 = (const float4*)(D + (size_t)wid * M1);
        warp_topk_d4<4, KK2>(drow4, lane, idx3 + (size_t)wid * KK2);
    } else if (blk < 576) {
        int i = blk - 512;
        gemm128_body<2>(Wd3, xm, y, 256, M1, 256, 256, M1, 0, 256L * M1,
                        nullptr, nullptr, nullptr, 0, 256, nullptr, 0,
                        i & 3, (i >> 2) & 1, i >> 3, S);
    } else {
        int i = blk - 576;
        gemm128_body<2>(Wu3, xm, u, 256, M1, 256, 256, M1, 0, 256L * M1,
                        nullptr, nullptr, nullptr, 0, 256, nullptr, 0,
                        i & 3, (i >> 2) & 1, i >> 3, S);
    }
}

// negdist4 (128) + y4 (64) + u4 (64) + maxv2a partial (256)
__global__ __launch_bounds__(256) void fusedA_kernel(
    const float* __restrict__ x34, const float* __restrict__ normA, float* __restrict__ D,
    const float* __restrict__ Wd4, const float* __restrict__ Wu4,
    float* __restrict__ y, float* __restrict__ u,
    const float* __restrict__ Wt2, float* __restrict__ P) {
    __shared__ SmemG S;
    int blk = blockIdx.x;
    if (blk < 128) {
        gemm128_body<0>(x34, x34, D, M1, M1, 256, M1, M1, 512L * M1, 512L * M1,
                        normA, normA, nullptr, 0, M1, nullptr, 0,
                        blk & 3, (blk >> 2) & 3, blk >> 4, S);
    } else if (blk < 192) {
        int i = blk - 128;
        gemm128_body<2>(Wd4, x34, y, 256, M1, 256, 256, M1, 0, 512L * M1,
                        nullptr, nullptr, nullptr, 0, 256, nullptr, 0,
                        i & 3, (i >> 2) & 1, i >> 3, S);
    } else if (blk < 256) {
        int i = blk - 192;
        gemm128_body<2>(Wu4, x34, u, 256, M1, 256, 256, M1, 0, 512L * M1,
                        nullptr, nullptr, nullptr, 0, 256, nullptr, 0,
                        i & 3, (i >> 2) & 1, i >> 3, S);
    } else {
        int i = blk - 256;
        gemm128_body<4>(Wt2, x34, nullptr, 1024, M1, 256, 1024, M1, 0, 512L * M1,
                        nullptr, nullptr, nullptr, 0, 0, P, M1,
                        i & 3, (i >> 2) & 7, i >> 5, S);
    }
}

// maxv2 final
__global__ __launch_bounds__(256) void maxv2b_kernel(
    const float* __restrict__ Wt2, const float* __restrict__ x34,
    const float* __restrict__ g5, const float* __restrict__ b5,
    unsigned* __restrict__ venc, float* __restrict__ P) {
    __shared__ SmemG S;
    int blk = blockIdx.x;
    gemm128_body<5>(Wt2 + 256 * 1024, x34 + 256L * M1, nullptr, 1024, M1, 256, 1024, M1,
                    0, 512L * M1, g5, b5, venc, 1024, 0, P, M1,
                    blk & 3, (blk >> 2) & 7, blk >> 5, S);
}

// ---------------- edge conv epilogue (layers 3..4) ----------------
template <int K, int DO_NORM>
__global__ void econv_kernel(const float* __restrict__ y, const float* __restrict__ u,
                             const int* __restrict__ idx, int O, int N,
                             const float* __restrict__ g, const float* __restrict__ bb,
                             float* __restrict__ out_cn, int Ctot, int coff,
                             float* __restrict__ out_nc, float* __restrict__ normOut) {
    __shared__ float s2[8];
    int o = threadIdx.x;
    int n = blockIdx.x;
    int b = blockIdx.y;
    const float* yb = y + (size_t)b * N * O;
    float uu = u[((size_t)b * N + n) * O + o];
    float gs = g[o] * BN_SCALE, bv = bb[o];
    const int* irow = idx + ((size_t)b * N + n) * K;
    int js[K];
#pragma unroll
    for (int t = 0; t < K; t++) js[t] = irow[t];
    float m = -CUDART_INF_F;
#pragma unroll
    for (int t = 0; t < K; t++) {
        float h = yb[(size_t)js[t] * O + o] + uu;
        h = h * gs + bv;
        h = h >= 0.f ? h : 0.2f * h;
        m = fmaxf(m, h);
    }
    out_cn[((size_t)b * Ctot + coff + o) * N + n] = m;
    if (out_nc) out_nc[((size_t)b * N + n) * Ctot + coff + o] = m;
    if (DO_NORM) {
        float sq = m * m;
#pragma unroll
        for (int off = 16; off > 0; off >>= 1)
            sq += __shfl_xor_sync(0xffffffffu, sq, off);
        int warp = o >> 5, lane = o & 31;
        if (lane == 0) s2[warp] = sq;
        __syncthreads();
        if (o == 0) {
            float s = s2[0];
            for (int w = 1; w < (O >> 5); w++) s += s2[w];
            normOut[b * N + n] = s;
        }
    }
}

__global__ void build_xm_kernel(const float* __restrict__ ft_nc, const int* __restrict__ fpsidx,
                                const int* __restrict__ idxA, float* __restrict__ xm,
                                float* __restrict__ normOut) {
    __shared__ float s2[4];
    int c = threadIdx.x;
    int m = blockIdx.x;
    int b = blockIdx.y;
    const float* fb = ft_nc + (size_t)b * N1 * 128;
    int j = fpsidx[b * M1 + m];
    float v1 = fb[(size_t)j * 128 + c];
    xm[((size_t)b * 256 + c) * M1 + m] = v1;
    const int* ir = idxA + ((size_t)b * M1 + m) * KK1;
    float mx = -CUDART_INF_F;
#pragma unroll
    for (int t = 0; t < KK1; t++) {
        int jj = ir[t];
        mx = fmaxf(mx, fb[(size_t)jj * 128 + c]);
    }
    xm[((size_t)b * 256 + 128 + c) * M1 + m] = mx;
    float sq = v1 * v1 + mx * mx;
#pragma unroll
    for (int off = 16; off > 0; off >>= 1)
        sq += __shfl_xor_sync(0xffffffffu, sq, off);
    int warp = c >> 5, lane = c & 31;
    if (lane == 0) s2[warp] = sq;
    __syncthreads();
    if (c == 0) normOut[b * M1 + m] = s2[0] + s2[1] + s2[2] + s2[3];
}

__global__ void head_kernel(const unsigned* __restrict__ venc,
                            const float* __restrict__ Wl1, const float* __restrict__ g6,
                            const float* __restrict__ b6, const float* __restrict__ Wl2,
                            const float* __restrict__ bl2, const float* __restrict__ g7,
                            const float* __restrict__ b7, const float* __restrict__ Wl3,
                            const float* __restrict__ bl3, float* __restrict__ out) {
    __shared__ float sv[2048];
    __shared__ float sh1[512];
    __shared__ float sh2[256];
    int b = blockIdx.x, tid = threadIdx.x;
    int w = tid >> 5, lane = tid & 31;
    for (int c = tid; c < 2048; c += 256) sv[c] = fdec(venc[b * 2048 + c]);
    __syncthreads();
    for (int o = w; o < 512; o += 8) {
        const float4* wr = (const float4*)(Wl1 + (size_t)o * 2048);
        float acc = 0.f;
#pragma unroll
        for (int j = 0; j < 16; j++) {
            float4 wv = wr[j * 32 + lane];
            const float4 s = *(const float4*)&sv[j * 128 + lane * 4];
            acc += wv.x * s.x + wv.y * s.y + wv.z * s.z + wv.w * s.w;
        }
#pragma unroll
        for (int off = 16; off > 0; off >>= 1)
            acc += __shfl_xor_sync(0xffffffffu, acc, off);
        if (lane == 0) {
            float h = acc * (g6[o] * BN_SCALE) + b6[o];
            sh1[o] = h >= 0.f ? h : 0.2f * h;
        }
    }
    __syncthreads();
    for (int o = w; o < 256; o += 8) {
        const float4* wr = (const float4*)(Wl2 + (size_t)o * 512);
        float acc = 0.f;
#pragma unroll
        for (int j = 0; j < 4; j++) {
            float4 wv = wr[j * 32 + lane];
            const float4 s = *(const float4*)&sh1[j * 128 + lane * 4];
            acc += wv.x * s.x + wv.y * s.y + wv.z * s.z + wv.w * s.w;
        }
#pragma unroll
        for (int off = 16; off > 0; off >>= 1)
            acc += __shfl_xor_sync(0xffffffffu, acc, off);
        if (lane == 0) {
            float h = (acc + bl2[o]) * (g7[o] * BN_SCALE) + b7[o];
            sh2[o] = h >= 0.f ? h : 0.2f * h;
        }
    }
    __syncthreads();
    for (int o = w; o < 40; o += 8) {
        const float4* wr = (const float4*)(Wl3 + (size_t)o * 256);
        float acc = 0.f;
#pragma unroll
        for (int j = 0; j < 2; j++) {
            float4 wv = wr[j * 32 + lane];
            const float4 s = *(const float4*)&sh2[j * 128 + lane * 4];
            acc += wv.x * s.x + wv.y * s.y + wv.z * s.z + wv.w * s.w;
        }
#pragma unroll
        for (int off = 16; off > 0; off >>= 1)
            acc += __shfl_xor_sync(0xffffffffu, acc, off);
        if (lane == 0) out[b * 40 + o] = acc + bl3[o];
    }
}

// ---------------- launch ----------------
extern "C" void kernel_launch(void* const* d_in, const int* in_sizes, int n_in,
                              void* d_out, int out_size) {
    const float* x   = (const float*)d_in[0];
    const float* W1  = (const float*)d_in[1];
    const float* g1  = (const float*)d_in[2];
    const float* b1  = (const float*)d_in[3];
    const float* W2  = (const float*)d_in[4];
    const float* g2  = (const float*)d_in[5];
    const float* b2  = (const float*)d_in[6];
    const float* W2m = (const float*)d_in[7];
    const float* g2m = (const float*)d_in[8];
    const float* b2m = (const float*)d_in[9];
    const float* W3  = (const float*)d_in[10];
    const float* g3  = (const float*)d_in[11];
    const float* b3  = (const float*)d_in[12];
    const float* W4  = (const float*)d_in[13];
    const float* g4  = (const float*)d_in[14];
    const float* b4  = (const float*)d_in[15];
    const float* W5  = (const float*)d_in[16];
    const float* g5  = (const float*)d_in[17];
    const float* b5  = (const float*)d_in[18];
    const float* Wl1 = (const float*)d_in[19];
    const float* g6  = (const float*)d_in[20];
    const float* b6  = (const float*)d_in[21];
    const float* Wl2 = (const float*)d_in[22];
    const float* bl2 = (const float*)d_in[23];
    const float* g7  = (const float*)d_in[24];
    const float* b7  = (const float*)d_in[25];
    const float* Wl3 = (const float*)d_in[26];
    const float* bl3 = (const float*)d_in[27];
    float* out = (float*)d_out;

    static float *pD = nullptr, *pP, *pNA, *pY, *pU, *pXt1cn, *pXt1nc,
                 *pNode1, *pXm, *pX34,
                 *pWd2, *pWu2, *pWd3, *pWu3, *pWd4, *pWu4, *pWt1, *pWt2;
    static unsigned *pVenc;
    static int *pIdxA, *pIdx3, *pIdx4, *pFps;
    if (!pD) {
        cudaGetSymbolAddress((void**)&pD, g_D);
        cudaGetSymbolAddress((void**)&pP, g_P);
        cudaGetSymbolAddress((void**)&pNA, g_normA);
        cudaGetSymbolAddress((void**)&pY, g_y);
        cudaGetSymbolAddress((void**)&pU, g_u);
        cudaGetSymbolAddress((void**)&pXt1cn, g_xt1_cn);
        cudaGetSymbolAddress((void**)&pXt1nc, g_xt1_nc);
        cudaGetSymbolAddress((void**)&pVenc, g_venc);
        cudaGetSymbolAddress((void**)&pNode1, g_node1);
        cudaGetSymbolAddress((void**)&pXm, g_xm);
        cudaGetSymbolAddress((void**)&pX34, g_x34);
        cudaGetSymbolAddress((void**)&pWd2, g_Wd2);
        cudaGetSymbolAddress((void**)&pWu2, g_Wu2);
        cudaGetSymbolAddress((void**)&pWd3, g_Wd3);
        cudaGetSymbolAddress((void**)&pWu3, g_Wu3);
        cudaGetSymbolAddress((void**)&pWd4, g_Wd4);
        cudaGetSymbolAddress((void**)&pWu4, g_Wu4);
        cudaGetSymbolAddress((void**)&pWt1, g_Wt1);
        cudaGetSymbolAddress((void**)&pWt2, g_Wt2);
        cudaGetSymbolAddress((void**)&pIdxA, g_idxA);
        cudaGetSymbolAddress((void**)&pIdx3, g_idx3);
        cudaGetSymbolAddress((void**)&pIdx4, g_idx4);
        cudaGetSymbolAddress((void**)&pFps, g_fpsidx);
    }

    // K1: knn1+econv1 fused + fps + weight preps + initv
    start_kernel<<<5208, 256>>>(x, W1, W2, W3, W4, W2m, W5, g1, b1,
                                pFps, pNode1, out + 320,
                                pWd2, pWu2, pWd3, pWu3, pWd4, pWu4,
                                pWt1, pWt2, pVenc, pXt1cn, pXt1nc, pNA);
    // K2: knn2 negdist + dual2 + aggregate knn
    mid2_kernel<<<2816, 256>>>(pXt1cn, pNA, pD, pWd2, pWu2, pY, pU, pNode1, x, pIdxA);
    // K3: topk2 + econv2 fused
    tk2econv_kernel<<<2048, 256>>>(pD, pY, pU, g2, b2, pXt1cn, pXt1nc);
    // K4: build xm (+ norms)
    build_xm_kernel<<<dim3(M1, BB), 128>>>(pXt1nc, pFps, pIdxA, pXm, pNA);
    // K5: knn3 negdist + maxv1 full
    nd3max_kernel<<<1152, 256>>>(pXm, pNA, pD, pWt1, pXt1cn, g2m, b2m, pVenc);
    // K6: topk3 + y3 + u3
    tk3_kernel<<<640, 256>>>(pD, pIdx3, pWd3, pWu3, pXm, pY, pU);
    // K7: econv3 (+ norms of x3)
    econv_kernel<KK2, 1><<<dim3(M1, BB), 256>>>(pY, pU, pIdx3, 256, M1, g3, b3,
                                                pX34, 512, 0, nullptr, pNA);
    // K8: knn4 negdist + y4 + u4 + maxv2a
    fusedA_kernel<<<512, 256>>>(pX34, pNA, pD, pWd4, pWu4, pY, pU, pWt2, pP);
    // K9: topk4
    topk_d4_kernel<4, KK2><<<512, 256>>>(pD, M1, M1, pIdx4);
    // K10: econv4
    econv_kernel<KK2, 0><<<dim3(M1, BB), 256>>>(pY, pU, pIdx4, 256, M1, g4, b4,
                                                pX34, 512, 256, nullptr, nullptr);
    // K11: maxv2b
    maxv2b_kernel<<<256, 256>>>(pWt2, pX34, g5, b5, pVenc, pP);
    // K12: head
    head_kernel<<<BB, 256>>>(pVenc, Wl1, g6, b6, Wl2, bl2, g7, b7, Wl3, bl3, out);
}

// round 17
// speedup vs baseline: 1.6147x; 1.0137x over previous
#include <cuda_runtime.h>
#include <math_constants.h>

#define BN_SCALE 0.9999950000374997f

#define BB 8
#define N1 2048
#define M1 512
#define KK1 20
#define KK2 10

// ---------------- scratch ----------------
__device__ float g_D[(size_t)BB * N1 * N1];
__device__ float g_P[BB * 1024 * M1];
__device__ float g_normA[BB * N1];
__device__ int   g_idxA[BB * M1 * KK1];
__device__ float g_y[BB * 131072];
__device__ float g_u[BB * 131072];
__device__ float g_xt1_cn[BB * 128 * N1];
__device__ float g_xt1_nc[BB * N1 * 128];
__device__ unsigned g_venc[BB * 2048];
__device__ int   g_fpsidx[BB * M1];
__device__ float g_node1[BB * 3 * M1];
__device__ float g_xm[BB * 256 * M1];
__device__ float g_x34[BB * 512 * M1];
__device__ float g_Wd2[64 * 64],   g_Wu2[64 * 64];
__device__ float g_Wd3[256 * 256], g_Wu3[256 * 256];
__device__ float g_Wd4[256 * 256], g_Wu4[256 * 256];
__device__ float g_Wt1[128 * 1024];
__device__ float g_Wt2[512 * 1024];

__device__ __forceinline__ unsigned fenc(float f) {
    unsigned u = __float_as_uint(f);
    return (u & 0x80000000u) ? ~u : (u | 0x80000000u);
}
__device__ __forceinline__ float fdec(unsigned u) {
    return __uint_as_float((u & 0x80000000u) ? (u & 0x7fffffffu) : ~u);
}

__device__ __forceinline__ bool tk_better(float a, int ia, float b, int ib) {
    return a > b || (a == b && ia < ib);
}

struct NullSink {
    __device__ __forceinline__ void operator()(int, int) const {}
};

// Sorted-insert with STRICT > (per-lane scan order is monotonic in index)
#define TK_INSERT(cv, ci)                                             \
    if ((cv) > bv3) {                                                 \
        if ((cv) > bv0) {                                             \
            bv3 = bv2; bi3 = bi2; bv2 = bv1; bi2 = bi1;               \
            bv1 = bv0; bi1 = bi0; bv0 = (cv); bi0 = (ci);             \
        } else if ((cv) > bv1) {                                      \
            bv3 = bv2; bi3 = bi2; bv2 = bv1; bi2 = bi1;               \
            bv1 = (cv); bi1 = (ci);                                   \
        } else if ((cv) > bv2) {                                      \
            bv3 = bv2; bi3 = bi2; bv2 = (cv); bi2 = (ci);             \
        } else {                                                      \
            bv3 = (cv); bi3 = (ci);                                   \
        }                                                             \
    }

// ---------------- streaming warp top-k: scalar functor source + per-round sink ----------------
template <int NPL, int KSEL, typename F, typename SK>
__device__ __forceinline__ void warp_topk_f(const F& getv, int lane, int* orow,
                                            const SK& sink) {
    unsigned long long zap = 0ull;
    float bv0, bv1, bv2, bv3;
    int bi0, bi1, bi2, bi3;

#define TK_RESET()                                                    \
    bv0 = bv1 = bv2 = bv3 = -CUDART_INF_F;                            \
    bi0 = bi1 = bi2 = bi3 = 1 << 30;

#define TK_SCAN_FIRST()                                               \
    {                                                                 \
        TK_RESET()                                                    \
        _Pragma("unroll")                                             \
        for (int s = 0; s < NPL; s++) {                               \
            float cv = getv(s);                                       \
            int ci = s * 32 + lane;                                   \
            TK_INSERT(cv, ci)                                         \
        }                                                             \
    }

#define TK_SCAN()                                                     \
    {                                                                 \
        TK_RESET()                                                    \
        _Pragma("unroll")                                             \
        for (int s = 0; s < NPL; s++) {                               \
            if ((zap >> s) & 1ull) continue;                          \
            float cv = getv(s);                                       \
            int ci = s * 32 + lane;                                   \
            TK_INSERT(cv, ci)                                         \
        }                                                             \
    }

    TK_SCAN_FIRST()
    for (int r = 0; r < KSEL; r++) {
        if (bi0 == (1 << 30)) { TK_SCAN() }
        float wb = bv0; int wi = bi0;
#pragma unroll
        for (int off = 16; off > 0; off >>= 1) {
            float ov = __shfl_xor_sync(0xffffffffu, wb, off);
            int oi = __shfl_xor_sync(0xffffffffu, wi, off);
            if (tk_better(ov, oi, wb, wi)) { wb = ov; wi = oi; }
        }
        if (orow && lane == 0) orow[r] = wi;
        sink(r, wi);
        if ((wi & 31) == lane) {
            zap |= 1ull << (wi >> 5);
            bv0 = bv1; bi0 = bi1;
            bv1 = bv2; bi1 = bi2;
            bv2 = bv3; bi2 = bi3;
            bv3 = -CUDART_INF_F; bi3 = 1 << 30;
        }
    }
#undef TK_SCAN
#undef TK_SCAN_FIRST
#undef TK_RESET
}

template <int NPL, int KSEL, typename F>
__device__ __forceinline__ void warp_topk_f(const F& getv, int lane, int* orow) {
    warp_topk_f<NPL, KSEL>(getv, lane, orow, NullSink{});
}

// ---------------- streaming warp top-k: float4 D-row source + per-round sink ----------------
template <int NCHUNK, int KSEL, typename SK>
__device__ __forceinline__ void warp_topk_d4(const float4* __restrict__ drow4, int lane,
                                             int* orow, const SK& sink) {
    unsigned long long zap = 0ull;
    float bv0, bv1, bv2, bv3;
    int bi0, bi1, bi2, bi3;

#define TK_RESET()                                                    \
    bv0 = bv1 = bv2 = bv3 = -CUDART_INF_F;                            \
    bi0 = bi1 = bi2 = bi3 = 1 << 30;

#define TK_SCAN_D4_FIRST()                                            \
    {                                                                 \
        TK_RESET()                                                    \
        _Pragma("unroll 4")                                           \
        for (int c = 0; c < NCHUNK; c++) {                            \
            float4 f = drow4[c * 32 + lane];                          \
            float vals[4] = {f.x, f.y, f.z, f.w};                     \
            _Pragma("unroll")                                         \
            for (int q = 0; q < 4; q++) {                             \
                float cv = vals[q];                                   \
                int ci = c * 128 + lane * 4 + q;                      \
                TK_INSERT(cv, ci)                                     \
            }                                                         \
        }                                                             \
    }

#define TK_SCAN_D4()                                                  \
    {                                                                 \
        TK_RESET()                                                    \
        _Pragma("unroll 4")                                           \
        for (int c = 0; c < NCHUNK; c++) {                            \
            float4 f = drow4[c * 32 + lane];                          \
            float vals[4] = {f.x, f.y, f.z, f.w};                     \
            _Pragma("unroll")                                         \
            for (int q = 0; q < 4; q++) {                             \
                int s = c * 4 + q;                                    \
                if ((zap >> s) & 1ull) continue;                      \
                float cv = vals[q];                                   \
                int ci = c * 128 + lane * 4 + q;                      \
                TK_INSERT(cv, ci)                                     \
            }                                                         \
        }                                                             \
    }

    TK_SCAN_D4_FIRST()
    for (int r = 0; r < KSEL; r++) {
        if (bi0 == (1 << 30)) { TK_SCAN_D4() }
        float wb = bv0; int wi = bi0;
#pragma unroll
        for (int off = 16; off > 0; off >>= 1) {
            float ov = __shfl_xor_sync(0xffffffffu, wb, off);
            int oi = __shfl_xor_sync(0xffffffffu, wi, off);
            if (tk_better(ov, oi, wb, wi)) { wb = ov; wi = oi; }
        }
        if (orow && lane == 0) orow[r] = wi;
        sink(r, wi);
        if (((wi >> 2) & 31) == lane) {
            int c = wi >> 7, q = wi & 3;
            zap |= 1ull << (c * 4 + q);
            bv0 = bv1; bi0 = bi1;
            bv1 = bv2; bi1 = bi2;
            bv2 = bv3; bi2 = bi3;
            bv3 = -CUDART_INF_F; bi3 = 1 << 30;
        }
    }
#undef TK_SCAN_D4
#undef TK_SCAN_D4_FIRST
#undef TK_RESET
}

template <int NCHUNK, int KSEL>
__device__ __forceinline__ void warp_topk_d4(const float4* __restrict__ drow4, int lane,
                                             int* orow) {
    warp_topk_d4<NCHUNK, KSEL>(drow4, lane, orow, NullSink{});
}

// ---------------- shared-memory structs ----------------
struct SmemStart {
    float a[N1], b[N1], c[N1], d[N1];
    float wv[2][8];
    int wi[2][8];
    int sIdx[M1];
};
struct SmemG {
    float As[2][8][128];
    float Bs[2][8][128];
};
struct SmemDual {
    float Wds[16][65];
    float Wus[16][65];
    float Xs[16][65];
};
union SmemMid2 { SmemG g; SmemDual d; SmemStart k; };

// ---------------- small bodies ----------------
__device__ void prepw_body(const float* __restrict__ W, float* __restrict__ WdT,
                           float* __restrict__ WuT, int O, int C, int vb) {
    int i = vb * 256 + threadIdx.x;
    if (i >= O * C) return;
    int o = i / C, c = i % C;
    float wd = W[o * 2 * C + c];
    float wc = W[o * 2 * C + C + c];
    WdT[(size_t)c * O + o] = wd;
    WuT[(size_t)c * O + o] = wc - wd;
}

__device__ void wtrans_body(const float* __restrict__ W, float* __restrict__ Wt,
                            int O, int C, int vb) {
    int i = vb * 256 + threadIdx.x;
    if (i >= O * C) return;
    int o = i / C, c = i % C;
    Wt[(size_t)c * O + o] = W[(size_t)o * C + c];
}

__device__ void initv_body(unsigned* venc, int vb) {
    int i = vb * 256 + threadIdx.x;
    if (i < BB * 2048) venc[i] = 0u;
}

// plain kNN (C=3) for aggregate
template <int KSEL>
__device__ void knn3d_body(const float* __restrict__ Q, const float* __restrict__ P,
                           int M, int* __restrict__ idxOut, long qbs, long pbs,
                           int mBase, int b, SmemStart& S) {
    int tid = threadIdx.x;
    int nt = blockDim.x;
    const float* Pb = P + (size_t)b * pbs;
    for (int j = tid; j < N1; j += nt) {
        float vx = Pb[j], vy = Pb[N1 + j], vz = Pb[2 * N1 + j];
        S.a[j] = vx; S.b[j] = vy; S.c[j] = vz;
        S.d[j] = __fadd_rn(__fadd_rn(__fmul_rn(vx, vx), __fmul_rn(vy, vy)),
                           __fmul_rn(vz, vz));
    }
    __syncthreads();
    int warp = tid >> 5, lane = tid & 31;
    int m = mBase + warp;
    const float* Qb = Q + (size_t)b * qbs;
    float qx = Qb[m], qy = Qb[M + m], qz = Qb[2 * M + m];
    auto getv = [&](int s) {
        int j = s * 32 + lane;
        float inner = fmaf(qx, S.a[j], fmaf(qy, S.b[j], qz * S.c[j]));
        return 2.f * inner - S.d[j];
    };
    warp_topk_f<64, KSEL>(getv, lane, idxOut + ((size_t)b * M + m) * KSEL);
}

// fused knn1 + econv1: per winner, all lanes update 2 channels (o=lane, o+32)
__device__ void knn1_econv_body(const float* __restrict__ x, const float* __restrict__ W1,
                                const float* __restrict__ g1, const float* __restrict__ b1,
                                float* __restrict__ out_cn, float* __restrict__ out_nc,
                                float* __restrict__ normOut,
                                int mBase, int b, SmemStart& S) {
    int tid = threadIdx.x;
    int nt = blockDim.x;
    const float* Pb = x + (size_t)b * 3 * N1;
    for (int j = tid; j < N1; j += nt) {
        float vx = Pb[j], vy = Pb[N1 + j], vz = Pb[2 * N1 + j];
        S.a[j] = vx; S.b[j] = vy; S.c[j] = vz;
        S.d[j] = __fadd_rn(__fadd_rn(__fmul_rn(vx, vx), __fmul_rn(vy, vy)),
                           __fmul_rn(vz, vz));
    }
    __syncthreads();
    int warp = tid >> 5, lane = tid & 31;
    int n = mBase + warp;
    float qx = Pb[n], qy = Pb[N1 + n], qz = Pb[2 * N1 + n];
    int o0 = lane, o1 = lane + 32;
    float wd00 = W1[o0 * 6 + 0], wd01 = W1[o0 * 6 + 1], wd02 = W1[o0 * 6 + 2];
    float wu00 = W1[o0 * 6 + 3] - wd00, wu01 = W1[o0 * 6 + 4] - wd01, wu02 = W1[o0 * 6 + 5] - wd02;
    float wd10 = W1[o1 * 6 + 0], wd11 = W1[o1 * 6 + 1], wd12 = W1[o1 * 6 + 2];
    float wu10 = W1[o1 * 6 + 3] - wd10, wu11 = W1[o1 * 6 + 4] - wd11, wu12 = W1[o1 * 6 + 5] - wd12;
    float uu0 = wu00 * qx + wu01 * qy + wu02 * qz;
    float uu1 = wu10 * qx + wu11 * qy + wu12 * qz;
    float gs0 = g1[o0] * BN_SCALE, bvv0 = b1[o0];
    float gs1 = g1[o1] * BN_SCALE, bvv1 = b1[o1];
    float m0 = -CUDART_INF_F, m1 = -CUDART_INF_F;
    auto getv = [&](int s) {
        int j = s * 32 + lane;
        float inner = fmaf(qx, S.a[j], fmaf(qy, S.b[j], qz * S.c[j]));
        return 2.f * inner - S.d[j];
    };
    auto sink = [&](int r, int wi) {
        float jx = S.a[wi], jy = S.b[wi], jz = S.c[wi];
        float h0 = wd00 * jx + wd01 * jy + wd02 * jz + uu0;
        h0 = h0 * gs0 + bvv0;
        h0 = h0 >= 0.f ? h0 : 0.2f * h0;
        m0 = fmaxf(m0, h0);
        float h1 = wd10 * jx + wd11 * jy + wd12 * jz + uu1;
        h1 = h1 * gs1 + bvv1;
        h1 = h1 >= 0.f ? h1 : 0.2f * h1;
        m1 = fmaxf(m1, h1);
    };
    warp_topk_f<64, KK1>(getv, lane, (int*)nullptr, sink);
    out_cn[((size_t)b * 128 + o0) * N1 + n] = m0;
    out_cn[((size_t)b * 128 + o1) * N1 + n] = m1;
    out_nc[((size_t)b * N1 + n) * 128 + o0] = m0;
    out_nc[((size_t)b * N1 + n) * 128 + o1] = m1;
    float sq = m0 * m0 + m1 * m1;
#pragma unroll
    for (int off = 16; off > 0; off >>= 1)
        sq += __shfl_xor_sync(0xffffffffu, sq, off);
    if (lane == 0) normOut[b * N1 + n] = sq;
}

__device__ void fps_body(const float* __restrict__ xyz, int* __restrict__ fpsidx,
                         float* __restrict__ node1, float* __restrict__ outNode,
                         int b, SmemStart& S) {
    int tid = threadIdx.x;
    int warp = tid >> 5, lane = tid & 31;
    const float* xb = xyz + (size_t)b * 3 * N1;
    for (int j = tid; j < N1; j += 256) {
        S.a[j] = xb[j];
        S.b[j] = xb[N1 + j];
        S.c[j] = xb[2 * N1 + j];
        S.d[j] = 1e10f;
    }
    __syncthreads();
    int last = 0;
    for (int it = 0; it < M1; it++) {
        int par = it & 1;
        if (tid == 0) { S.sIdx[it] = last; fpsidx[b * M1 + it] = last; }
        float px = S.a[last], py = S.b[last], pz = S.c[last];
        float bmax = -CUDART_INF_F;
        int bidx = 0;
#pragma unroll
        for (int r = 0; r < 8; r++) {
            int j = tid + r * 256;
            float dx = __fsub_rn(S.a[j], px);
            float dy = __fsub_rn(S.b[j], py);
            float dz = __fsub_rn(S.c[j], pz);
            float dd = __fadd_rn(__fadd_rn(__fmul_rn(dx, dx), __fmul_rn(dy, dy)),
                                 __fmul_rn(dz, dz));
            float nd = fminf(S.d[j], dd);
            S.d[j] = nd;
            if (nd > bmax) { bmax = nd; bidx = j; }
        }
#pragma unroll
        for (int off = 16; off > 0; off >>= 1) {
            float ov = __shfl_xor_sync(0xffffffffu, bmax, off);
            int oi = __shfl_xor_sync(0xffffffffu, bidx, off);
            if (ov > bmax || (ov == bmax && oi < bidx)) { bmax = ov; bidx = oi; }
        }
        if (lane == 0) { S.wv[par][warp] = bmax; S.wi[par][warp] = bidx; }
        __syncthreads();
        float bv = S.wv[par][0];
        int bi = S.wi[par][0];
#pragma unroll
        for (int w = 1; w < 8; w++) {
            float ov = S.wv[par][w];
            int oi = S.wi[par][w];
            if (ov > bv || (ov == bv && oi < bi)) { bv = ov; bi = oi; }
        }
        last = bi;
    }
    __syncthreads();
    for (int m = tid; m < M1; m += 256) {
        int j = S.sIdx[m];
        float vx = S.a[j], vy = S.b[j], vz = S.c[j];
        node1[((size_t)b * 3 + 0) * M1 + m] = vx;
        node1[((size_t)b * 3 + 1) * M1 + m] = vy;
        node1[((size_t)b * 3 + 2) * M1 + m] = vz;
        outNode[((size_t)b * 3 + 0) * M1 + m] = vx;
        outNode[((size_t)b * 3 + 1) * M1 + m] = vy;
        outNode[((size_t)b * 3 + 2) * M1 + m] = vz;
    }
}

__device__ void gemm_dual_body(const float* __restrict__ WdT, const float* __restrict__ WuT,
                               const float* __restrict__ X,
                               float* __restrict__ y, float* __restrict__ u,
                               int O, int C, int N, long xbs,
                               int bx, int by, int bz, SmemDual& S) {
    int o0 = by * 64, n0 = bx * 64;
    int t = threadIdx.x;
    int tx = t & 15, ty = t >> 4;
    const float* Xb = X + (size_t)bz * xbs;
    float accd[4][4], accu[4][4];
#pragma unroll
    for (int i = 0; i < 4; i++)
#pragma unroll
        for (int j = 0; j < 4; j++) { accd[i][j] = 0.f; accu[i][j] = 0.f; }

    for (int c0 = 0; c0 < C; c0 += 16) {
#pragma unroll
        for (int l = 0; l < 4; l++) {
            int e = t + l * 256;
            int wo = e & 63, wc = e >> 6;
            float vd = 0.f, vu = 0.f;
            if (o0 + wo < O && c0 + wc < C) {
                vd = WdT[(size_t)(c0 + wc) * O + o0 + wo];
                vu = WuT[(size_t)(c0 + wc) * O + o0 + wo];
            }
            S.Wds[wc][wo] = vd;
            S.Wus[wc][wo] = vu;
            float xv = 0.f;
            if (c0 + wc < C && n0 + wo < N) xv = Xb[(size_t)(c0 + wc) * N + n0 + wo];
            S.Xs[wc][wo] = xv;
        }
        __syncthreads();
#pragma unroll
        for (int kk = 0; kk < 16; kk++) {
            float wd[4], wu[4], xv[4];
#pragma unroll
            for (int i = 0; i < 4; i++) { wd[i] = S.Wds[kk][ty + 16 * i]; wu[i] = S.Wus[kk][ty + 16 * i]; }
#pragma unroll
            for (int j = 0; j < 4; j++) xv[j] = S.Xs[kk][tx + 16 * j];
#pragma unroll
            for (int i = 0; i < 4; i++)
#pragma unroll
                for (int j = 0; j < 4; j++) {
                    accd[i][j] += wd[i] * xv[j];
                    accu[i][j] += wu[i] * xv[j];
                }
        }
        __syncthreads();
    }
#pragma unroll
    for (int i = 0; i < 4; i++) {
        int o = o0 + ty + 16 * i;
        if (o >= O) continue;
#pragma unroll
        for (int j = 0; j < 4; j++) {
            int n = n0 + tx + 16 * j;
            if (n >= N) continue;
            y[((size_t)bz * N + n) * O + o] = accd[i][j];
            u[((size_t)bz * N + n) * O + o] = accu[i][j];
        }
    }
}

// ================= 128x128x8 GEMM body =================
template <int MODE>
__device__ void gemm128_body(
    const float* __restrict__ A, const float* __restrict__ B, float* __restrict__ out,
    int M, int N, int C, long ldA, long ldB, long abs_, long bbs,
    const float* __restrict__ p1, const float* __restrict__ p2,
    unsigned* __restrict__ venc, int voff, int ldOut,
    float* __restrict__ P, int ldP,
    int bx, int by, int bz, SmemG& S) {
    int m0 = by * 128, n0 = bx * 128;
    int t = threadIdx.x;
    int tx = t & 15, ty = t >> 4;
    int lr = t >> 5;
    int lc = (t & 31) * 4;
    const float* aSrc = A + (size_t)bz * abs_ + (size_t)lr * ldA + m0 + lc;
    const float* bSrc = B + (size_t)bz * bbs + (size_t)lr * ldB + n0 + lc;
    float acc[8][8];
#pragma unroll
    for (int i = 0; i < 8; i++)
#pragma unroll
        for (int j = 0; j < 8; j++) acc[i][j] = 0.f;

    int nc = C >> 3;
    float4 av = *(const float4*)aSrc;
    float4 bv = *(const float4*)bSrc;
    *(float4*)&S.As[0][lr][lc] = av;
    *(float4*)&S.Bs[0][lr][lc] = bv;
    __syncthreads();
    int p = 0;
    for (int i = 0; i < nc; i++) {
        if (i + 1 < nc) {
            av = *(const float4*)(aSrc + (size_t)(i + 1) * 8 * ldA);
            bv = *(const float4*)(bSrc + (size_t)(i + 1) * 8 * ldB);
        }
#pragma unroll
        for (int k = 0; k < 8; k++) {
            float4 a0 = *(float4*)&S.As[p][k][ty * 4];
            float4 a1 = *(float4*)&S.As[p][k][64 + ty * 4];
            float4 b0 = *(float4*)&S.Bs[p][k][tx * 4];
            float4 b1 = *(float4*)&S.Bs[p][k][64 + tx * 4];
            float aa[8] = {a0.x, a0.y, a0.z, a0.w, a1.x, a1.y, a1.z, a1.w};
            float bb[8] = {b0.x, b0.y, b0.z, b0.w, b1.x, b1.y, b1.z, b1.w};
#pragma unroll
            for (int ii = 0; ii < 8; ii++)
#pragma unroll
                for (int jj = 0; jj < 8; jj++) acc[ii][jj] += aa[ii] * bb[jj];
        }
        if (i + 1 < nc) {
            *(float4*)&S.As[p ^ 1][lr][lc] = av;
            *(float4*)&S.Bs[p ^ 1][lr][lc] = bv;
            __syncthreads();
            p ^= 1;
        }
    }

    if (MODE == 0) {
#pragma unroll
        for (int i = 0; i < 8; i++) {
            int m = m0 + (i < 4 ? ty * 4 + i : 64 + ty * 4 + i - 4);
            float nq = p1[bz * M + m];
            float* orow = out + ((size_t)bz * M + m) * ldOut;
            float4 d0, d1;
            d0.x = 2.f * acc[i][0] - nq - p2[bz * N + n0 + tx * 4 + 0];
            d0.y = 2.f * acc[i][1] - nq - p2[bz * N + n0 + tx * 4 + 1];
            d0.z = 2.f * acc[i][2] - nq - p2[bz * N + n0 + tx * 4 + 2];
            d0.w = 2.f * acc[i][3] - nq - p2[bz * N + n0 + tx * 4 + 3];
            d1.x = 2.f * acc[i][4] - nq - p2[bz * N + n0 + 64 + tx * 4 + 0];
            d1.y = 2.f * acc[i][5] - nq - p2[bz * N + n0 + 64 + tx * 4 + 1];
            d1.z = 2.f * acc[i][6] - nq - p2[bz * N + n0 + 64 + tx * 4 + 2];
            d1.w = 2.f * acc[i][7] - nq - p2[bz * N + n0 + 64 + tx * 4 + 3];
            *(float4*)&orow[n0 + tx * 4] = d0;
            *(float4*)&orow[n0 + 64 + tx * 4] = d1;
        }
    } else if (MODE == 1 || MODE == 5) {
        if (MODE == 5) {
#pragma unroll
            for (int i = 0; i < 8; i++) {
                int m = m0 + (i < 4 ? ty * 4 + i : 64 + ty * 4 + i - 4);
                const float* prow = P + ((size_t)bz * M + m) * ldP;
                float4 q0 = *(const float4*)&prow[n0 + tx * 4];
                float4 q1 = *(const float4*)&prow[n0 + 64 + tx * 4];
                acc[i][0] += q0.x; acc[i][1] += q0.y; acc[i][2] += q0.z; acc[i][3] += q0.w;
                acc[i][4] += q1.x; acc[i][5] += q1.y; acc[i][6] += q1.z; acc[i][7] += q1.w;
            }
        }
#pragma unroll
        for (int i = 0; i < 8; i++) {
            int m = m0 + (i < 4 ? ty * 4 + i : 64 + ty * 4 + i - 4);
            float gs = p1[m] * BN_SCALE, bvv = p2[m];
            float mx = -CUDART_INF_F;
#pragma unroll
            for (int j = 0; j < 8; j++) {
                float h = acc[i][j] * gs + bvv;
                h = h >= 0.f ? h : 0.2f * h;
                mx = fmaxf(mx, h);
            }
#pragma unroll
            for (int off = 8; off > 0; off >>= 1)
                mx = fmaxf(mx, __shfl_xor_sync(0xffffffffu, mx, off));
            if (tx == 0) atomicMax(&venc[bz * 2048 + voff + m], fenc(mx));
        }
    } else if (MODE == 4) {
#pragma unroll
        for (int i = 0; i < 8; i++) {
            int m = m0 + (i < 4 ? ty * 4 + i : 64 + ty * 4 + i - 4);
            float* prow = P + ((size_t)bz * M + m) * ldP;
            float4 v0, v1;
            v0.x = acc[i][0]; v0.y = acc[i][1]; v0.z = acc[i][2]; v0.w = acc[i][3];
            v1.x = acc[i][4]; v1.y = acc[i][5]; v1.z = acc[i][6]; v1.w = acc[i][7];
            *(float4*)&prow[n0 + tx * 4] = v0;
            *(float4*)&prow[n0 + 64 + tx * 4] = v1;
        }
    } else {
#pragma unroll
        for (int jj = 0; jj < 8; jj++) {
            int n = n0 + (jj < 4 ? tx * 4 + jj : 64 + tx * 4 + jj - 4);
            float* orow = out + ((size_t)bz * N + n) * ldOut;
            float4 v0, v1;
            v0.x = acc[0][jj]; v0.y = acc[1][jj]; v0.z = acc[2][jj]; v0.w = acc[3][jj];
            v1.x = acc[4][jj]; v1.y = acc[5][jj]; v1.z = acc[6][jj]; v1.w = acc[7][jj];
            *(float4*)&orow[m0 + ty * 4] = v0;
            *(float4*)&orow[m0 + 64 + ty * 4] = v1;
        }
    }
}

// ---------------- dispatcher kernels ----------------
__global__ __launch_bounds__(256) void start_kernel(
    const float* __restrict__ x,
    const float* __restrict__ W1, const float* __restrict__ W2,
    const float* __restrict__ W3, const float* __restrict__ W4,
    const float* __restrict__ W2m, const float* __restrict__ W5,
    const float* __restrict__ g1, const float* __restrict__ b1,
    int* __restrict__ fpsidx,
    float* __restrict__ node1, float* __restrict__ outNode,
    float* Wd2, float* Wu2,
    float* Wd3, float* Wu3, float* Wd4, float* Wu4,
    float* Wt1, float* Wt2, unsigned* venc,
    float* __restrict__ xt1cn, float* __restrict__ xt1nc, float* __restrict__ normA) {
    __shared__ SmemStart S;
    int blk = blockIdx.x;
    if (blk < 2048) {
        knn1_econv_body(x, W1, g1, b1, xt1cn, xt1nc, normA, (blk & 255) * 8, blk >> 8, S);
    } else if (blk < 2056) {
        fps_body(x, fpsidx, node1, outNode, blk - 2048, S);
    } else if (blk < 2072) {
        prepw_body(W2, Wd2, Wu2, 64, 64, blk - 2056);
    } else if (blk < 2328) {
        prepw_body(W3, Wd3, Wu3, 256, 256, blk - 2072);
    } else if (blk < 2584) {
        prepw_body(W4, Wd4, Wu4, 256, 256, blk - 2328);
    } else if (blk < 3096) {
        wtrans_body(W2m, Wt1, 1024, 128, blk - 2584);
    } else if (blk < 5144) {
        wtrans_body(W5, Wt2, 1024, 512, blk - 3096);
    } else {
        initv_body(venc, blk - 5144);
    }
}

// knn2 negdist (2048) + dual2 (256) + aggregate knn (512)
__global__ __launch_bounds__(256) void mid2_kernel(
    const float* __restrict__ xt1cn, const float* __restrict__ normA, float* __restrict__ D,
    const float* __restrict__ Wd2, const float* __restrict__ Wu2,
    float* __restrict__ y, float* __restrict__ u,
    const float* __restrict__ node1, const float* __restrict__ x, int* __restrict__ idxA) {
    __shared__ SmemMid2 S;
    int blk = blockIdx.x;
    if (blk < 2048) {
        gemm128_body<0>(xt1cn, xt1cn, D, N1, N1, 64, N1, N1, 128L * N1, 128L * N1,
                        normA, normA, nullptr, 0, N1, nullptr, 0,
                        blk & 15, (blk >> 4) & 15, blk >> 8, S.g);
    } else if (blk < 2304) {
        int i = blk - 2048;
        gemm_dual_body(Wd2, Wu2, xt1cn, y, u, 64, 64, N1, 128L * N1, i & 31, 0, i >> 5, S.d);
    } else {
        int i = blk - 2304;
        knn3d_body<KK1>(node1, x, M1, idxA, 3L * M1, 3L * N1, (i & 63) * 8, i >> 6, S.k);
    }
}

// fused topk2 + econv2
__global__ __launch_bounds__(256, 3) void tk2econv_kernel(
    const float* __restrict__ D, const float* __restrict__ y, const float* __restrict__ u,
    const float* __restrict__ g2, const float* __restrict__ b2,
    float* __restrict__ out_cn, float* __restrict__ out_nc) {
    int warp = threadIdx.x >> 5, lane = threadIdx.x & 31;
    int wid = blockIdx.x * 8 + warp;
    int b = wid >> 11, n = wid & 2047;
    const float4* drow4 = (const float4*)(D + (size_t)wid * N1);
    int w[KK1];
    auto sink = [&](int r, int wi) { w[r] = wi; };
    warp_topk_d4<16, KK1>(drow4, lane, (int*)nullptr, sink);
    int o0 = lane, o1 = lane + 32;
    const float* yb = y + (size_t)b * N1 * 64;
    float uu0 = u[((size_t)b * N1 + n) * 64 + o0];
    float uu1 = u[((size_t)b * N1 + n) * 64 + o1];
    float gs0 = g2[o0] * BN_SCALE, bv0 = b2[o0];
    float gs1 = g2[o1] * BN_SCALE, bv1 = b2[o1];
    float m0 = -CUDART_INF_F, m1 = -CUDART_INF_F;
#pragma unroll
    for (int r = 0; r < KK1; r++) {
        int j = w[r];
        float h0 = yb[(size_t)j * 64 + o0] + uu0;
        h0 = h0 * gs0 + bv0;
        h0 = h0 >= 0.f ? h0 : 0.2f * h0;
        m0 = fmaxf(m0, h0);
        float h1 = yb[(size_t)j * 64 + o1] + uu1;
        h1 = h1 * gs1 + bv1;
        h1 = h1 >= 0.f ? h1 : 0.2f * h1;
        m1 = fmaxf(m1, h1);
    }
    out_cn[((size_t)b * 128 + 64 + o0) * N1 + n] = m0;
    out_cn[((size_t)b * 128 + 64 + o1) * N1 + n] = m1;
    out_nc[((size_t)b * N1 + n) * 128 + 64 + o0] = m0;
    out_nc[((size_t)b * N1 + n) * 128 + 64 + o1] = m1;
}

// fused topk3/4 + econv3/4 (8 channels per lane), optional norm output
template <int DO_NORM>
__global__ __launch_bounds__(256) void tkMecon_kernel(
    const float* __restrict__ D, const float* __restrict__ y, const float* __restrict__ u,
    const float* __restrict__ g, const float* __restrict__ bb,
    float* __restrict__ out_cn, int coff, float* __restrict__ normOut) {
    int warp = threadIdx.x >> 5, lane = threadIdx.x & 31;
    int wid = blockIdx.x * 8 + warp;
    int b = wid >> 9, m = wid & 511;
    const float4* drow4 = (const float4*)(D + (size_t)wid * M1);
    int w[KK2];
    auto sink = [&](int r, int wi) { w[r] = wi; };
    warp_topk_d4<4, KK2>(drow4, lane, (int*)nullptr, sink);
    // econv: 8 channels o = lane + 32*k
    const float* yb = y + (size_t)b * M1 * 256;
    const float* ub = u + ((size_t)b * M1 + m) * 256;
    float uu[8], gs[8], bv[8], mx[8];
#pragma unroll
    for (int k = 0; k < 8; k++) {
        int o = lane + 32 * k;
        uu[k] = ub[o];
        gs[k] = g[o] * BN_SCALE;
        bv[k] = bb[o];
        mx[k] = -CUDART_INF_F;
    }
#pragma unroll
    for (int r = 0; r < KK2; r++) {
        const float* yr = yb + (size_t)w[r] * 256;
#pragma unroll
        for (int k = 0; k < 8; k++) {
            float h = yr[lane + 32 * k] + uu[k];
            h = h * gs[k] + bv[k];
            h = h >= 0.f ? h : 0.2f * h;
            mx[k] = fmaxf(mx[k], h);
        }
    }
    float sq = 0.f;
#pragma unroll
    for (int k = 0; k < 8; k++) {
        int o = lane + 32 * k;
        out_cn[((size_t)b * 512 + coff + o) * M1 + m] = mx[k];
        if (DO_NORM) sq += mx[k] * mx[k];
    }
    if (DO_NORM) {
#pragma unroll
        for (int off = 16; off > 0; off >>= 1)
            sq += __shfl_xor_sync(0xffffffffu, sq, off);
        if (lane == 0) normOut[b * M1 + m] = sq;
    }
}

// negdist3 (128) + maxv1 full C=128 (1024) + y3 (64) + u3 (64)
__global__ __launch_bounds__(256) void nd3max_kernel(
    const float* __restrict__ xm, const float* __restrict__ normA, float* __restrict__ D,
    const float* __restrict__ Wt1, const float* __restrict__ xt1cn,
    const float* __restrict__ g2m, const float* __restrict__ b2m,
    unsigned* __restrict__ venc,
    const float* __restrict__ Wd3, const float* __restrict__ Wu3,
    float* __restrict__ y, float* __restrict__ u) {
    __shared__ SmemG S;
    int blk = blockIdx.x;
    if (blk < 128) {
        gemm128_body<0>(xm, xm, D, M1, M1, 256, M1, M1, 256L * M1, 256L * M1,
                        normA, normA, nullptr, 0, M1, nullptr, 0,
                        blk & 3, (blk >> 2) & 3, blk >> 4, S);
    } else if (blk < 1152) {
        int i = blk - 128;
        gemm128_body<1>(Wt1, xt1cn, nullptr, 1024, N1, 128, 1024, N1, 0, 128L * N1,
                        g2m, b2m, venc, 0, 0, nullptr, 0,
                        i & 15, (i >> 4) & 7, i >> 7, S);
    } else if (blk < 1216) {
        int i = blk - 1152;
        gemm128_body<2>(Wd3, xm, y, 256, M1, 256, 256, M1, 0, 256L * M1,
                        nullptr, nullptr, nullptr, 0, 256, nullptr, 0,
                        i & 3, (i >> 2) & 1, i >> 3, S);
    } else {
        int i = blk - 1216;
        gemm128_body<2>(Wu3, xm, u, 256, M1, 256, 256, M1, 0, 256L * M1,
                        nullptr, nullptr, nullptr, 0, 256, nullptr, 0,
                        i & 3, (i >> 2) & 1, i >> 3, S);
    }
}

// negdist4 (128) + y4 (64) + u4 (64) + maxv2a partial (256)
__global__ __launch_bounds__(256) void fusedA_kernel(
    const float* __restrict__ x34, const float* __restrict__ normA, float* __restrict__ D,
    const float* __restrict__ Wd4, const float* __restrict__ Wu4,
    float* __restrict__ y, float* __restrict__ u,
    const float* __restrict__ Wt2, float* __restrict__ P) {
    __shared__ SmemG S;
    int blk = blockIdx.x;
    if (blk < 128) {
        gemm128_body<0>(x34, x34, D, M1, M1, 256, M1, M1, 512L * M1, 512L * M1,
                        normA, normA, nullptr, 0, M1, nullptr, 0,
                        blk & 3, (blk >> 2) & 3, blk >> 4, S);
    } else if (blk < 192) {
        int i = blk - 128;
        gemm128_body<2>(Wd4, x34, y, 256, M1, 256, 256, M1, 0, 512L * M1,
                        nullptr, nullptr, nullptr, 0, 256, nullptr, 0,
                        i & 3, (i >> 2) & 1, i >> 3, S);
    } else if (blk < 256) {
        int i = blk - 192;
        gemm128_body<2>(Wu4, x34, u, 256, M1, 256, 256, M1, 0, 512L * M1,
                        nullptr, nullptr, nullptr, 0, 256, nullptr, 0,
                        i & 3, (i >> 2) & 1, i >> 3, S);
    } else {
        int i = blk - 256;
        gemm128_body<4>(Wt2, x34, nullptr, 1024, M1, 256, 1024, M1, 0, 512L * M1,
                        nullptr, nullptr, nullptr, 0, 0, P, M1,
                        i & 3, (i >> 2) & 7, i >> 5, S);
    }
}

// maxv2 final
__global__ __launch_bounds__(256) void maxv2b_kernel(
    const float* __restrict__ Wt2, const float* __restrict__ x34,
    const float* __restrict__ g5, const float* __restrict__ b5,
    unsigned* __restrict__ venc, float* __restrict__ P) {
    __shared__ SmemG S;
    int blk = blockIdx.x;
    gemm128_body<5>(Wt2 + 256 * 1024, x34 + 256L * M1, nullptr, 1024, M1, 256, 1024, M1,
                    0, 512L * M1, g5, b5, venc, 1024, 0, P, M1,
                    blk & 3, (blk >> 2) & 7, blk >> 5, S);
}

__global__ void build_xm_kernel(const float* __restrict__ ft_nc, const int* __restrict__ fpsidx,
                                const int* __restrict__ idxA, float* __restrict__ xm,
                                float* __restrict__ normOut) {
    __shared__ float s2[4];
    int c = threadIdx.x;
    int m = blockIdx.x;
    int b = blockIdx.y;
    const float* fb = ft_nc + (size_t)b * N1 * 128;
    int j = fpsidx[b * M1 + m];
    float v1 = fb[(size_t)j * 128 + c];
    xm[((size_t)b * 256 + c) * M1 + m] = v1;
    const int* ir = idxA + ((size_t)b * M1 + m) * KK1;
    float mx = -CUDART_INF_F;
#pragma unroll
    for (int t = 0; t < KK1; t++) {
        int jj = ir[t];
        mx = fmaxf(mx, fb[(size_t)jj * 128 + c]);
    }
    xm[((size_t)b * 256 + 128 + c) * M1 + m] = mx;
    float sq = v1 * v1 + mx * mx;
#pragma unroll
    for (int off = 16; off > 0; off >>= 1)
        sq += __shfl_xor_sync(0xffffffffu, sq, off);
    int warp = c >> 5, lane = c & 31;
    if (lane == 0) s2[warp] = sq;
    __syncthreads();
    if (c == 0) normOut[b * M1 + m] = s2[0] + s2[1] + s2[2] + s2[3];
}

__global__ void head_kernel(const unsigned* __restrict__ venc,
                            const float* __restrict__ Wl1, const float* __restrict__ g6,
                            const float* __restrict__ b6, const float* __restrict__ Wl2,
                            const float* __restrict__ bl2, const float* __restrict__ g7,
                            const float* __restrict__ b7, const float* __restrict__ Wl3,
                            const float* __restrict__ bl3, float* __restrict__ out) {
    __shared__ float sv[2048];
    __shared__ float sh1[512];
    __shared__ float sh2[256];
    int b = blockIdx.x, tid = threadIdx.x;
    int w = tid >> 5, lane = tid & 31;
    for (int c = tid; c < 2048; c += 256) sv[c] = fdec(venc[b * 2048 + c]);
    __syncthreads();
    for (int o = w; o < 512; o += 8) {
        const float4* wr = (const float4*)(Wl1 + (size_t)o * 2048);
        float acc = 0.f;
#pragma unroll
        for (int j = 0; j < 16; j++) {
            float4 wv = wr[j * 32 + lane];
            const float4 s = *(const float4*)&sv[j * 128 + lane * 4];
            acc += wv.x * s.x + wv.y * s.y + wv.z * s.z + wv.w * s.w;
        }
#pragma unroll
        for (int off = 16; off > 0; off >>= 1)
            acc += __shfl_xor_sync(0xffffffffu, acc, off);
        if (lane == 0) {
            float h = acc * (g6[o] * BN_SCALE) + b6[o];
            sh1[o] = h >= 0.f ? h : 0.2f * h;
        }
    }
    __syncthreads();
    for (int o = w; o < 256; o += 8) {
        const float4* wr = (const float4*)(Wl2 + (size_t)o * 512);
        float acc = 0.f;
#pragma unroll
        for (int j = 0; j < 4; j++) {
            float4 wv = wr[j * 32 + lane];
            const float4 s = *(const float4*)&sh1[j * 128 + lane * 4];
            acc += wv.x * s.x + wv.y * s.y + wv.z * s.z + wv.w * s.w;
        }
#pragma unroll
        for (int off = 16; off > 0; off >>= 1)
            acc += __shfl_xor_sync(0xffffffffu, acc, off);
        if (lane == 0) {
            float h = (acc + bl2[o]) * (g7[o] * BN_SCALE) + b7[o];
            sh2[o] = h >= 0.f ? h : 0.2f * h;
        }
    }
    __syncthreads();
    for (int o = w; o < 40; o += 8) {
        const float4* wr = (const float4*)(Wl3 + (size_t)o * 256);
        float acc = 0.f;
#pragma unroll
        for (int j = 0; j < 2; j++) {
            float4 wv = wr[j * 32 + lane];
            const float4 s = *(const float4*)&sh2[j * 128 + lane * 4];
            acc += wv.x * s.x + wv.y * s.y + wv.z * s.z + wv.w * s.w;
        }
#pragma unroll
        for (int off = 16; off > 0; off >>= 1)
            acc += __shfl_xor_sync(0xffffffffu, acc, off);
        if (lane == 0) out[b * 40 + o] = acc + bl3[o];
    }
}

// ---------------- launch ----------------
extern "C" void kernel_launch(void* const* d_in, const int* in_sizes, int n_in,
                              void* d_out, int out_size) {
    const float* x   = (const float*)d_in[0];
    const float* W1  = (const float*)d_in[1];
    const float* g1  = (const float*)d_in[2];
    const float* b1  = (const float*)d_in[3];
    const float* W2  = (const float*)d_in[4];
    const float* g2  = (const float*)d_in[5];
    const float* b2  = (const float*)d_in[6];
    const float* W2m = (const float*)d_in[7];
    const float* g2m = (const float*)d_in[8];
    const float* b2m = (const float*)d_in[9];
    const float* W3  = (const float*)d_in[10];
    const float* g3  = (const float*)d_in[11];
    const float* b3  = (const float*)d_in[12];
    const float* W4  = (const float*)d_in[13];
    const float* g4  = (const float*)d_in[14];
    const float* b4  = (const float*)d_in[15];
    const float* W5  = (const float*)d_in[16];
    const float* g5  = (const float*)d_in[17];
    const float* b5  = (const float*)d_in[18];
    const float* Wl1 = (const float*)d_in[19];
    const float* g6  = (const float*)d_in[20];
    const float* b6  = (const float*)d_in[21];
    const float* Wl2 = (const float*)d_in[22];
    const float* bl2 = (const float*)d_in[23];
    const float* g7  = (const float*)d_in[24];
    const float* b7  = (const float*)d_in[25];
    const float* Wl3 = (const float*)d_in[26];
    const float* bl3 = (const float*)d_in[27];
    float* out = (float*)d_out;

    static float *pD = nullptr, *pP, *pNA, *pY, *pU, *pXt1cn, *pXt1nc,
                 *pNode1, *pXm, *pX34,
                 *pWd2, *pWu2, *pWd3, *pWu3, *pWd4, *pWu4, *pWt1, *pWt2;
    static unsigned *pVenc;
    static int *pIdxA, *pFps;
    if (!pD) {
        cudaGetSymbolAddress((void**)&pD, g_D);
        cudaGetSymbolAddress((void**)&pP, g_P);
        cudaGetSymbolAddress((void**)&pNA, g_normA);
        cudaGetSymbolAddress((void**)&pY, g_y);
        cudaGetSymbolAddress((void**)&pU, g_u);
        cudaGetSymbolAddress((void**)&pXt1cn, g_xt1_cn);
        cudaGetSymbolAddress((void**)&pXt1nc, g_xt1_nc);
        cudaGetSymbolAddress((void**)&pVenc, g_venc);
        cudaGetSymbolAddress((void**)&pNode1, g_node1);
        cudaGetSymbolAddress((void**)&pXm, g_xm);
        cudaGetSymbolAddress((void**)&pX34, g_x34);
        cudaGetSymbolAddress((void**)&pWd2, g_Wd2);
        cudaGetSymbolAddress((void**)&pWu2, g_Wu2);
        cudaGetSymbolAddress((void**)&pWd3, g_Wd3);
        cudaGetSymbolAddress((void**)&pWu3, g_Wu3);
        cudaGetSymbolAddress((void**)&pWd4, g_Wd4);
        cudaGetSymbolAddress((void**)&pWu4, g_Wu4);
        cudaGetSymbolAddress((void**)&pWt1, g_Wt1);
        cudaGetSymbolAddress((void**)&pWt2, g_Wt2);
        cudaGetSymbolAddress((void**)&pIdxA, g_idxA);
        cudaGetSymbolAddress((void**)&pFps, g_fpsidx);
    }

    // K1: knn1+econv1 fused + fps + weight preps + initv
    start_kernel<<<5208, 256>>>(x, W1, W2, W3, W4, W2m, W5, g1, b1,
                                pFps, pNode1, out + 320,
                                pWd2, pWu2, pWd3, pWu3, pWd4, pWu4,
                                pWt1, pWt2, pVenc, pXt1cn, pXt1nc, pNA);
    // K2: knn2 negdist + dual2 + aggregate knn
    mid2_kernel<<<2816, 256>>>(pXt1cn, pNA, pD, pWd2, pWu2, pY, pU, pNode1, x, pIdxA);
    // K3: topk2 + econv2 fused
    tk2econv_kernel<<<2048, 256>>>(pD, pY, pU, g2, b2, pXt1cn, pXt1nc);
    // K4: build xm (+ norms)
    build_xm_kernel<<<dim3(M1, BB), 128>>>(pXt1nc, pFps, pIdxA, pXm, pNA);
    // K5: knn3 negdist + maxv1 full + y3 + u3
    nd3max_kernel<<<1280, 256>>>(pXm, pNA, pD, pWt1, pXt1cn, g2m, b2m, pVenc,
                                 pWd3, pWu3, pY, pU);
    // K6: topk3 + econv3 fused (+ norms of x3)
    tkMecon_kernel<1><<<512, 256>>>(pD, pY, pU, g3, b3, pX34, 0, pNA);
    // K7: knn4 negdist + y4 + u4 + maxv2a
    fusedA_kernel<<<512, 256>>>(pX34, pNA, pD, pWd4, pWu4, pY, pU, pWt2, pP);
    // K8: topk4 + econv4 fused
    tkMecon_kernel<0><<<512, 256>>>(pD, pY, pU, g4, b4, pX34, 256, nullptr);
    // K9: maxv2b
    maxv2b_kernel<<<256, 256>>>(pWt2, pX34, g5, b5, pVenc, pP);
    // K10: head
    head_kernel<<<BB, 256>>>(pVenc, Wl1, g6, b6, Wl2, bl2, g7, b7, Wl3, bl3, out);
}